// round 8
// baseline (speedup 1.0000x reference)
#include <cuda_runtime.h>
#include <cstdint>

#define N_NODES 100000
#define N_EDGES 1600000
#define IN_CH   128
#define HIDDEN  64
#define NCLS    40

// ---------------- scratch (device globals; no allocation allowed) ----------
__device__ int   g_is64;
__device__ int   g_deg[N_NODES];
__device__ int   g_off[N_NODES + 1];
__device__ int   g_cur[N_NODES];
__device__ float g_dinv[N_NODES];
__device__ int   g_bsum[128];
__device__ int2  g_adj[N_EDGES];                     // (src, norm-as-bits), grouped by dst
__device__ float g_hw  [(size_t)N_NODES * HIDDEN];   // X @ W1
__device__ float g_agg1[(size_t)N_NODES * HIDDEN];   // layer1 aggregated (pre-relu)
__device__ float g_h2w [(size_t)N_NODES * NCLS];     // relu(agg1) @ W2

// ---------------- packed f32x2 helpers --------------------------------------
__device__ __forceinline__ unsigned long long ffma2(unsigned long long a,
                                                    unsigned long long b,
                                                    unsigned long long c) {
    unsigned long long d;
    asm("fma.rn.f32x2 %0, %1, %2, %3;" : "=l"(d) : "l"(a), "l"(b), "l"(c));
    return d;
}
__device__ __forceinline__ unsigned long long pack2(float a) {
    unsigned long long d;
    asm("mov.b64 %0, {%1, %1};" : "=l"(d) : "f"(a));
    return d;
}

// ---------------- prep: zero degrees + detect index dtype -------------------
// int64 indices (<2^31) have zero high words at every odd int32 position.
__global__ void prep_kernel(const int* __restrict__ w) {
    int i = blockIdx.x * blockDim.x + threadIdx.x;
    if (i < N_NODES) g_deg[i] = 0;
    if (blockIdx.x == 0) {
        __shared__ int acc;
        if (threadIdx.x == 0) acc = 0;
        __syncthreads();
        int v = 0;
        for (int j = threadIdx.x; j < 4096; j += blockDim.x) v |= w[2 * j + 1];
        atomicOr(&acc, v);
        __syncthreads();
        if (threadIdx.x == 0) g_is64 = (acc == 0) ? 1 : 0;
    }
}

#define NB_EDGE4 1563                    // ceil(1.6M / (256*4))
#define EDGE4_T  (NB_EDGE4 * 256)

__global__ void deg_kernel(const int* __restrict__ w) {
    int idx = blockIdx.x * 256 + threadIdx.x;
    int is64 = g_is64;
#pragma unroll
    for (int j = 0; j < 4; j++) {
        int e = idx + j * EDGE4_T;
        if (e < N_EDGES) {
            int d = is64 ? w[2 * (N_EDGES + e)] : w[N_EDGES + e];
            if ((unsigned)d >= N_NODES) d = 0;
            atomicAdd(&g_deg[d], 1);
        }
    }
}

// ---------------- scan: A = per-block sums; C = full scan (B fused) ---------
#define SCAN_NB  128
#define SCAN_TPB 256
#define SCAN_PER 4        // 128*256*4 = 131072 >= N_NODES

__global__ void scanA_kernel() {
    __shared__ int red[SCAN_TPB];
    int t = threadIdx.x;
    int base = (blockIdx.x * SCAN_TPB + t) * SCAN_PER;
    int s = 0;
#pragma unroll
    for (int j = 0; j < SCAN_PER; j++) {
        int i = base + j;
        if (i < N_NODES) s += g_deg[i];
    }
    red[t] = s;
    __syncthreads();
    for (int o = SCAN_TPB / 2; o > 0; o >>= 1) {
        if (t < o) red[t] += red[t + o];
        __syncthreads();
    }
    if (t == 0) g_bsum[blockIdx.x] = red[0];
}

// scanC: every block redundantly scans the 128 block sums (cheap), then its
// own per-element exclusive scan; writes g_off, g_cur, g_dinv.
__global__ void scanC_kernel() {
    __shared__ int top[SCAN_NB];
    __shared__ int p[SCAN_TPB];
    int t = threadIdx.x;

    if (t < SCAN_NB) top[t] = g_bsum[t];
    __syncthreads();
    for (int o = 1; o < SCAN_NB; o <<= 1) {
        int v = (t >= o && t < SCAN_NB) ? top[t - o] : 0;
        __syncthreads();
        if (t < SCAN_NB) top[t] += v;
        __syncthreads();
    }
    int bpre = (blockIdx.x > 0) ? top[blockIdx.x - 1] : 0;
    if (blockIdx.x == SCAN_NB - 1 && t == 0) g_off[N_NODES] = top[SCAN_NB - 1];

    int base = (blockIdx.x * SCAN_TPB + t) * SCAN_PER;
    int loc[SCAN_PER];
    int s = 0;
#pragma unroll
    for (int j = 0; j < SCAN_PER; j++) {
        int i = base + j;
        int d = (i < N_NODES) ? g_deg[i] : 0;
        loc[j] = s;
        s += d;
    }
    p[t] = s;
    __syncthreads();
    for (int o = 1; o < SCAN_TPB; o <<= 1) {
        int v = (t >= o) ? p[t - o] : 0;
        __syncthreads();
        p[t] += v;
        __syncthreads();
    }
    int pre = bpre + ((t > 0) ? p[t - 1] : 0);
#pragma unroll
    for (int j = 0; j < SCAN_PER; j++) {
        int i = base + j;
        if (i < N_NODES) {
            int o = pre + loc[j];
            g_off[i] = o;
            g_cur[i] = o;
            g_dinv[i] = rsqrtf((float)(g_deg[i] + 1));  // +1 self loop
        }
    }
}

// counting-sort edges by dst into g_adj (re-decodes ei; norm precomputed)
__global__ void fill_kernel(const int* __restrict__ w) {
    int idx = blockIdx.x * 256 + threadIdx.x;
    int is64 = g_is64;
#pragma unroll
    for (int j = 0; j < 4; j++) {
        int e = idx + j * EDGE4_T;
        if (e < N_EDGES) {
            int s, d;
            if (is64) { s = w[2 * e]; d = w[2 * (N_EDGES + e)]; }
            else      { s = w[e];     d = w[N_EDGES + e]; }
            if ((unsigned)s >= N_NODES) s = 0;
            if ((unsigned)d >= N_NODES) d = 0;
            int pos = atomicAdd(&g_cur[d], 1);
            g_adj[pos] = make_int2(s, __float_as_int(g_dinv[s] * g_dinv[d]));
        }
    }
}

// ---------------- GEMM1: C[M,64] = A[M,128] * W[128,64] --------------------
// 128 rows/block, 256 threads, 4x8 micro-tile with packed fma.rn.f32x2.
__global__ void gemm1_kernel(const float* __restrict__ A,
                             const float* __restrict__ W,
                             float* __restrict__ C, int M) {
    constexpr int KDIM = IN_CH, NDIM = HIDDEN, ROWS = 128, NT = 256;
    constexpr int PITCH = KDIM + 4;
    extern __shared__ float smem[];
    float* sA = smem;                   // [128][132]
    float* sW = smem + ROWS * PITCH;    // [128][64]
    const int tid = threadIdx.x;
    const int rowbase = blockIdx.x * ROWS;

    for (int v = tid; v < KDIM * NDIM / 4; v += NT)
        ((float4*)sW)[v] = ((const float4*)W)[v];

    constexpr int KC4 = KDIM / 4;
    for (int v = tid; v < ROWS * KC4; v += NT) {
        int r  = v / KC4;
        int kc = (v - r * KC4) * 4;
        int row = rowbase + r;
        float4 a = make_float4(0.f, 0.f, 0.f, 0.f);
        if (row < M) a = *(const float4*)(A + (size_t)row * KDIM + kc);
        *(float4*)(sA + r * PITCH + kc) = a;
    }
    __syncthreads();

    const int ty = tid / 8, tx = tid & 7;   // 32 x 8
    unsigned long long acc[4][4];
#pragma unroll
    for (int i = 0; i < 4; i++)
#pragma unroll
        for (int j = 0; j < 4; j++) acc[i][j] = 0ull;

#pragma unroll 4
    for (int k = 0; k < KDIM; k++) {
        ulonglong2 b01 = *(const ulonglong2*)(sW + k * NDIM + 8 * tx);
        ulonglong2 b23 = *(const ulonglong2*)(sW + k * NDIM + 8 * tx + 4);
#pragma unroll
        for (int i = 0; i < 4; i++) {
            unsigned long long pa = pack2(sA[(4 * ty + i) * PITCH + k]);
            acc[i][0] = ffma2(pa, b01.x, acc[i][0]);
            acc[i][1] = ffma2(pa, b01.y, acc[i][1]);
            acc[i][2] = ffma2(pa, b23.x, acc[i][2]);
            acc[i][3] = ffma2(pa, b23.y, acc[i][3]);
        }
    }

#pragma unroll
    for (int i = 0; i < 4; i++) {
        int row = rowbase + 4 * ty + i;
        if (row < M) {
            ulonglong2* p = (ulonglong2*)(C + (size_t)row * NDIM + 8 * tx);
            p[0] = make_ulonglong2(acc[i][0], acc[i][1]);
            p[1] = make_ulonglong2(acc[i][2], acc[i][3]);
        }
    }
}

// ---------------- GEMM2: C[M,40] = relu(A[M,64]) * W[64,40] ----------------
__global__ void gemm2_kernel(const float* __restrict__ A,
                             const float* __restrict__ W,
                             float* __restrict__ C, int M) {
    constexpr int KDIM = HIDDEN, NDIM = NCLS, ROWS = 128;
    constexpr int TX = NDIM / 8, TY = ROWS / 4, NT = TX * TY;  // 5 x 32 = 160
    constexpr int PITCH = KDIM + 4;
    extern __shared__ float smem[];
    float* sA = smem;
    float* sW = smem + ROWS * PITCH;

    const int tid     = threadIdx.x;
    const int rowbase = blockIdx.x * ROWS;

    for (int v = tid; v < KDIM * NDIM / 4; v += NT)
        ((float4*)sW)[v] = ((const float4*)W)[v];

    constexpr int KC4 = KDIM / 4;
    for (int v = tid; v < ROWS * KC4; v += NT) {
        int r  = v / KC4;
        int kc = (v - r * KC4) * 4;
        int row = rowbase + r;
        float4 a = make_float4(0.f, 0.f, 0.f, 0.f);
        if (row < M) a = *(const float4*)(A + (size_t)row * KDIM + kc);
        a.x = fmaxf(a.x, 0.f); a.y = fmaxf(a.y, 0.f);
        a.z = fmaxf(a.z, 0.f); a.w = fmaxf(a.w, 0.f);
        *(float4*)(sA + r * PITCH + kc) = a;
    }
    __syncthreads();

    const int ty = tid / TX, tx = tid - (tid / TX) * TX;
    unsigned long long acc[4][4];
#pragma unroll
    for (int i = 0; i < 4; i++)
#pragma unroll
        for (int j = 0; j < 4; j++) acc[i][j] = 0ull;

#pragma unroll 4
    for (int k = 0; k < KDIM; k++) {
        ulonglong2 b01 = *(const ulonglong2*)(sW + k * NDIM + 8 * tx);
        ulonglong2 b23 = *(const ulonglong2*)(sW + k * NDIM + 8 * tx + 4);
#pragma unroll
        for (int i = 0; i < 4; i++) {
            unsigned long long pa = pack2(sA[(4 * ty + i) * PITCH + k]);
            acc[i][0] = ffma2(pa, b01.x, acc[i][0]);
            acc[i][1] = ffma2(pa, b01.y, acc[i][1]);
            acc[i][2] = ffma2(pa, b23.x, acc[i][2]);
            acc[i][3] = ffma2(pa, b23.y, acc[i][3]);
        }
    }

#pragma unroll
    for (int i = 0; i < 4; i++) {
        int row = rowbase + 4 * ty + i;
        if (row < M) {
            ulonglong2* p = (ulonglong2*)(C + (size_t)row * NDIM + 8 * tx);
            p[0] = make_ulonglong2(acc[i][0], acc[i][1]);
            p[1] = make_ulonglong2(acc[i][2], acc[i][3]);
        }
    }
}

// ---------------- CSR aggregation with adj prefetch -------------------------
// out[i] = bias + dinv_i^2*feat[i] + sum_j norm_ij*feat[src_j]
// one warp per node; lane groups of V4 lanes own float4 chunks; EP edges/iter.
template<int CH>
__global__ void aggregate_kernel(const float* __restrict__ feat,
                                 const float* __restrict__ bias,
                                 float* __restrict__ out) {
    constexpr int V4 = CH / 4;       // 16 (CH=64) or 10 (CH=40)
    constexpr int EP = 32 / V4;      // 2 or 3
    int node = (blockIdx.x * blockDim.x + threadIdx.x) >> 5;
    if (node >= N_NODES) return;
    int lane = threadIdx.x & 31;
    int eg = lane / V4;              // edge group
    int c  = lane - eg * V4;         // float4 index within row
    bool act = eg < EP;

    const int beg = g_off[node];
    const int end = g_off[node + 1];

    float4 acc = make_float4(0.f, 0.f, 0.f, 0.f);
    if (eg == 0) {                   // self-loop + bias in group 0 only
        float dv = g_dinv[node];
        float s  = dv * dv;
        float4 f  = ((const float4*)(feat + (size_t)node * CH))[c];
        float4 bb = ((const float4*)bias)[c];
        acc.x = fmaf(s, f.x, bb.x);
        acc.y = fmaf(s, f.y, bb.y);
        acc.z = fmaf(s, f.z, bb.z);
        acc.w = fmaf(s, f.w, bb.w);
    }

    // software-pipelined edge loop; dummy entries carry norm=0 (src=0 safe)
    int2 p = make_int2(0, 0);
    if (act && beg + eg < end) p = g_adj[beg + eg];
    for (int k = beg; k < end; k += EP) {
        int kn = k + EP;
        int2 pn = make_int2(0, 0);
        if (act && kn + eg < end) pn = g_adj[kn + eg];
        float nrm = __int_as_float(p.y);
        float4 v = ((const float4*)(feat + (size_t)p.x * CH))[c];
        acc.x = fmaf(nrm, v.x, acc.x);
        acc.y = fmaf(nrm, v.y, acc.y);
        acc.z = fmaf(nrm, v.z, acc.z);
        acc.w = fmaf(nrm, v.w, acc.w);
        p = pn;
    }

    // reduce groups 1..EP-1 into group 0 (shfls read pre-update values)
    const unsigned m = 0xffffffffu;
    float x1 = __shfl_down_sync(m, acc.x, V4);
    float y1 = __shfl_down_sync(m, acc.y, V4);
    float z1 = __shfl_down_sync(m, acc.z, V4);
    float w1 = __shfl_down_sync(m, acc.w, V4);
    if (EP > 2) {
        float x2 = __shfl_down_sync(m, acc.x, 2 * V4);
        float y2 = __shfl_down_sync(m, acc.y, 2 * V4);
        float z2 = __shfl_down_sync(m, acc.z, 2 * V4);
        float w2 = __shfl_down_sync(m, acc.w, 2 * V4);
        x1 += x2; y1 += y2; z1 += z2; w1 += w2;
    }
    acc.x += x1; acc.y += y1; acc.z += z1; acc.w += w1;

    if (eg == 0)
        ((float4*)(out + (size_t)node * CH))[c] = acc;
}

// ---------------- launch ----------------------------------------------------
extern "C" void kernel_launch(void* const* d_in, const int* in_sizes, int n_in,
                              void* d_out, int out_size) {
    const float* x  = (const float*)d_in[0];
    const int*   ei = (const int*)d_in[1];      // int32 words of edge_index (either dtype)
    const float* W1 = (const float*)d_in[2];
    const float* b1 = (const float*)d_in[3];
    const float* W2 = (const float*)d_in[4];
    const float* b2 = (const float*)d_in[5];
    float*       out = (float*)d_out;

    void *hw_p, *agg1_p, *h2w_p;
    cudaGetSymbolAddress(&hw_p,   g_hw);
    cudaGetSymbolAddress(&agg1_p, g_agg1);
    cudaGetSymbolAddress(&h2w_p,  g_h2w);

    constexpr int TPB = 256;
    const int nb_nodes = (N_NODES + TPB - 1) / TPB;

    // fork-join: gemm1 (independent of edge preprocessing) runs on a second
    // stream captured via event fork from the main stream. Handles are created
    // per call and intentionally not destroyed (destroying a forked stream
    // mid-capture invalidates the capture; kernel_launch runs only a few times
    // on the host, graph replays don't re-execute host code).
    cudaStream_t s2;
    cudaEvent_t evF, evJ;
    cudaStreamCreateWithFlags(&s2, cudaStreamNonBlocking);
    cudaEventCreateWithFlags(&evF, cudaEventDisableTiming);
    cudaEventCreateWithFlags(&evJ, cudaEventDisableTiming);

    cudaEventRecord(evF, 0);
    cudaStreamWaitEvent(s2, evF, 0);

    // ---- side stream: gemm1 X @ W1 ----
    constexpr int SMEM1 = (128 * (IN_CH + 4) + IN_CH * HIDDEN) * sizeof(float); // 100352
    cudaFuncSetAttribute(gemm1_kernel, cudaFuncAttributeMaxDynamicSharedMemorySize, SMEM1);
    gemm1_kernel<<<(N_NODES + 127) / 128, 256, SMEM1, s2>>>(x, W1, (float*)hw_p, N_NODES);
    cudaEventRecord(evJ, s2);

    // ---- main stream: edge preprocessing ----
    prep_kernel<<<nb_nodes, TPB>>>(ei);
    deg_kernel<<<NB_EDGE4, 256>>>(ei);
    scanA_kernel<<<SCAN_NB, SCAN_TPB>>>();
    scanC_kernel<<<SCAN_NB, SCAN_TPB>>>();
    fill_kernel<<<NB_EDGE4, 256>>>(ei);

    // join: agg1 needs both g_hw (s2) and g_adj (main)
    cudaStreamWaitEvent(0, evJ, 0);

    const int nb_warps = (N_NODES * 32 + TPB - 1) / TPB;  // 1 warp per node
    aggregate_kernel<HIDDEN><<<nb_warps, TPB>>>((const float*)hw_p, b1, (float*)agg1_p);

    constexpr int SMEM2 = (128 * (HIDDEN + 4) + HIDDEN * NCLS) * sizeof(float); // 45056
    cudaFuncSetAttribute(gemm2_kernel, cudaFuncAttributeMaxDynamicSharedMemorySize, SMEM2);
    gemm2_kernel<<<(N_NODES + 127) / 128, 160, SMEM2>>>((const float*)agg1_p, W2,
                                                        (float*)h2w_p, N_NODES);

    aggregate_kernel<NCLS><<<nb_warps, TPB>>>((const float*)h2w_p, b2, out);
}

// round 9
// speedup vs baseline: 1.1083x; 1.1083x over previous
#include <cuda_runtime.h>
#include <cuda_fp16.h>
#include <cstdint>

#define N_NODES 100000
#define N_EDGES 1600000
#define IN_CH   128
#define HIDDEN  64
#define NCLS    40

// ---------------- scratch (device globals; no allocation allowed) ----------
__device__ int   g_is64;
__device__ int   g_deg[N_NODES];       // zero-initialized at load; re-zeroed by agg2 tail
__device__ int   g_off[N_NODES + 1];
__device__ int   g_cur[N_NODES];
__device__ float g_dinv[N_NODES];
__device__ int   g_bsum[128];
__device__ int2  g_adj[N_EDGES];                     // (src, norm-as-bits), grouped by dst
__device__ __align__(16) __half g_hw [(size_t)N_NODES * HIDDEN];  // X @ W1 (fp16)
__device__ float g_agg1[(size_t)N_NODES * HIDDEN];                // layer1 agg (fp32)
__device__ __align__(16) __half g_h2w[(size_t)N_NODES * NCLS];    // relu(agg1) @ W2 (fp16)

// ---------------- packed f32x2 helpers --------------------------------------
__device__ __forceinline__ unsigned long long ffma2(unsigned long long a,
                                                    unsigned long long b,
                                                    unsigned long long c) {
    unsigned long long d;
    asm("fma.rn.f32x2 %0, %1, %2, %3;" : "=l"(d) : "l"(a), "l"(b), "l"(c));
    return d;
}
__device__ __forceinline__ unsigned long long pack2(float a) {
    unsigned long long d;
    asm("mov.b64 %0, {%1, %1};" : "=l"(d) : "f"(a));
    return d;
}
// 8 halfs (uint4) -> 8 floats
__device__ __forceinline__ void h8_to_f8(uint4 v, float* f) {
    float2 t;
    t = __half22float2(*(__half2*)&v.x); f[0] = t.x; f[1] = t.y;
    t = __half22float2(*(__half2*)&v.y); f[2] = t.x; f[3] = t.y;
    t = __half22float2(*(__half2*)&v.z); f[4] = t.x; f[5] = t.y;
    t = __half22float2(*(__half2*)&v.w); f[6] = t.x; f[7] = t.y;
}
// one f32x2 accumulator (2 floats) -> half2 bits
__device__ __forceinline__ unsigned f2_to_h2(unsigned long long a) {
    float2 f = *(float2*)&a;
    __half2 h = __float22half2_rn(f);
    return *(unsigned*)&h;
}

// ---------------- detect index dtype ----------------------------------------
// int64 indices (<2^31) have zero high words at every odd int32 position.
__global__ void detect_kernel(const int* __restrict__ w) {
    __shared__ int acc;
    if (threadIdx.x == 0) acc = 0;
    __syncthreads();
    int v = 0;
    for (int j = threadIdx.x; j < 4096; j += blockDim.x) v |= w[2 * j + 1];
    atomicOr(&acc, v);
    __syncthreads();
    if (threadIdx.x == 0) g_is64 = (acc == 0) ? 1 : 0;
}

#define NB_EDGE4 1563                    // ceil(1.6M / (256*4))
#define EDGE4_T  (NB_EDGE4 * 256)

// g_deg is zero on entry (module init / previous call's agg2 tail)
__global__ void deg_kernel(const int* __restrict__ w) {
    int idx = blockIdx.x * 256 + threadIdx.x;
    int is64 = g_is64;
#pragma unroll
    for (int j = 0; j < 4; j++) {
        int e = idx + j * EDGE4_T;
        if (e < N_EDGES) {
            int d = is64 ? w[2 * (N_EDGES + e)] : w[N_EDGES + e];
            if ((unsigned)d >= N_NODES) d = 0;
            atomicAdd(&g_deg[d], 1);
        }
    }
}

// ---------------- scan: A = per-block sums; C = full scan ------------------
#define SCAN_NB  128
#define SCAN_TPB 256
#define SCAN_PER 4        // 128*256*4 = 131072 >= N_NODES

__global__ void scanA_kernel() {
    __shared__ int red[SCAN_TPB];
    int t = threadIdx.x;
    int base = (blockIdx.x * SCAN_TPB + t) * SCAN_PER;
    int s = 0;
#pragma unroll
    for (int j = 0; j < SCAN_PER; j++) {
        int i = base + j;
        if (i < N_NODES) s += g_deg[i];
    }
    red[t] = s;
    __syncthreads();
    for (int o = SCAN_TPB / 2; o > 0; o >>= 1) {
        if (t < o) red[t] += red[t + o];
        __syncthreads();
    }
    if (t == 0) g_bsum[blockIdx.x] = red[0];
}

__global__ void scanC_kernel() {
    __shared__ int top[SCAN_NB];
    __shared__ int p[SCAN_TPB];
    int t = threadIdx.x;

    if (t < SCAN_NB) top[t] = g_bsum[t];
    __syncthreads();
    for (int o = 1; o < SCAN_NB; o <<= 1) {
        int v = (t >= o && t < SCAN_NB) ? top[t - o] : 0;
        __syncthreads();
        if (t < SCAN_NB) top[t] += v;
        __syncthreads();
    }
    int bpre = (blockIdx.x > 0) ? top[blockIdx.x - 1] : 0;
    if (blockIdx.x == SCAN_NB - 1 && t == 0) g_off[N_NODES] = top[SCAN_NB - 1];

    int base = (blockIdx.x * SCAN_TPB + t) * SCAN_PER;
    int loc[SCAN_PER];
    int s = 0;
#pragma unroll
    for (int j = 0; j < SCAN_PER; j++) {
        int i = base + j;
        int d = (i < N_NODES) ? g_deg[i] : 0;
        loc[j] = s;
        s += d;
    }
    p[t] = s;
    __syncthreads();
    for (int o = 1; o < SCAN_TPB; o <<= 1) {
        int v = (t >= o) ? p[t - o] : 0;
        __syncthreads();
        p[t] += v;
        __syncthreads();
    }
    int pre = bpre + ((t > 0) ? p[t - 1] : 0);
#pragma unroll
    for (int j = 0; j < SCAN_PER; j++) {
        int i = base + j;
        if (i < N_NODES) {
            int o = pre + loc[j];
            g_off[i] = o;
            g_cur[i] = o;
            g_dinv[i] = rsqrtf((float)(g_deg[i] + 1));  // +1 self loop
        }
    }
}

// counting-sort edges by dst into g_adj (re-decodes ei; norm precomputed)
__global__ void fill_kernel(const int* __restrict__ w) {
    int idx = blockIdx.x * 256 + threadIdx.x;
    int is64 = g_is64;
#pragma unroll
    for (int j = 0; j < 4; j++) {
        int e = idx + j * EDGE4_T;
        if (e < N_EDGES) {
            int s, d;
            if (is64) { s = w[2 * e]; d = w[2 * (N_EDGES + e)]; }
            else      { s = w[e];     d = w[N_EDGES + e]; }
            if ((unsigned)s >= N_NODES) s = 0;
            if ((unsigned)d >= N_NODES) d = 0;
            int pos = atomicAdd(&g_cur[d], 1);
            g_adj[pos] = make_int2(s, __float_as_int(g_dinv[s] * g_dinv[d]));
        }
    }
}

// ---------------- GEMM1: fp16 C[M,64] = A[M,128] * W[128,64] ----------------
__global__ void gemm1_kernel(const float* __restrict__ A,
                             const float* __restrict__ W,
                             __half* __restrict__ C, int M) {
    constexpr int KDIM = IN_CH, NDIM = HIDDEN, ROWS = 128, NT = 256;
    constexpr int PITCH = KDIM + 4;
    extern __shared__ float smem[];
    float* sA = smem;                   // [128][132]
    float* sW = smem + ROWS * PITCH;    // [128][64]
    const int tid = threadIdx.x;
    const int rowbase = blockIdx.x * ROWS;

    for (int v = tid; v < KDIM * NDIM / 4; v += NT)
        ((float4*)sW)[v] = ((const float4*)W)[v];

    constexpr int KC4 = KDIM / 4;
    for (int v = tid; v < ROWS * KC4; v += NT) {
        int r  = v / KC4;
        int kc = (v - r * KC4) * 4;
        int row = rowbase + r;
        float4 a = make_float4(0.f, 0.f, 0.f, 0.f);
        if (row < M) a = *(const float4*)(A + (size_t)row * KDIM + kc);
        *(float4*)(sA + r * PITCH + kc) = a;
    }
    __syncthreads();

    const int ty = tid / 8, tx = tid & 7;   // 32 x 8
    unsigned long long acc[4][4];
#pragma unroll
    for (int i = 0; i < 4; i++)
#pragma unroll
        for (int j = 0; j < 4; j++) acc[i][j] = 0ull;

#pragma unroll 4
    for (int k = 0; k < KDIM; k++) {
        ulonglong2 b01 = *(const ulonglong2*)(sW + k * NDIM + 8 * tx);
        ulonglong2 b23 = *(const ulonglong2*)(sW + k * NDIM + 8 * tx + 4);
#pragma unroll
        for (int i = 0; i < 4; i++) {
            unsigned long long pa = pack2(sA[(4 * ty + i) * PITCH + k]);
            acc[i][0] = ffma2(pa, b01.x, acc[i][0]);
            acc[i][1] = ffma2(pa, b01.y, acc[i][1]);
            acc[i][2] = ffma2(pa, b23.x, acc[i][2]);
            acc[i][3] = ffma2(pa, b23.y, acc[i][3]);
        }
    }

#pragma unroll
    for (int i = 0; i < 4; i++) {
        int row = rowbase + 4 * ty + i;
        if (row < M) {
            uint4 u;
            u.x = f2_to_h2(acc[i][0]);
            u.y = f2_to_h2(acc[i][1]);
            u.z = f2_to_h2(acc[i][2]);
            u.w = f2_to_h2(acc[i][3]);
            *(uint4*)(C + (size_t)row * NDIM + 8 * tx) = u;
        }
    }
}

// ---------------- GEMM2: fp16 C[M,40] = relu(A[M,64]) * W[64,40] -----------
__global__ void gemm2_kernel(const float* __restrict__ A,
                             const float* __restrict__ W,
                             __half* __restrict__ C, int M) {
    constexpr int KDIM = HIDDEN, NDIM = NCLS, ROWS = 128;
    constexpr int TX = NDIM / 8, TY = ROWS / 4, NT = TX * TY;  // 5 x 32 = 160
    constexpr int PITCH = KDIM + 4;
    extern __shared__ float smem[];
    float* sA = smem;
    float* sW = smem + ROWS * PITCH;

    const int tid     = threadIdx.x;
    const int rowbase = blockIdx.x * ROWS;

    for (int v = tid; v < KDIM * NDIM / 4; v += NT)
        ((float4*)sW)[v] = ((const float4*)W)[v];

    constexpr int KC4 = KDIM / 4;
    for (int v = tid; v < ROWS * KC4; v += NT) {
        int r  = v / KC4;
        int kc = (v - r * KC4) * 4;
        int row = rowbase + r;
        float4 a = make_float4(0.f, 0.f, 0.f, 0.f);
        if (row < M) a = *(const float4*)(A + (size_t)row * KDIM + kc);
        a.x = fmaxf(a.x, 0.f); a.y = fmaxf(a.y, 0.f);
        a.z = fmaxf(a.z, 0.f); a.w = fmaxf(a.w, 0.f);
        *(float4*)(sA + r * PITCH + kc) = a;
    }
    __syncthreads();

    const int ty = tid / TX, tx = tid - (tid / TX) * TX;
    unsigned long long acc[4][4];
#pragma unroll
    for (int i = 0; i < 4; i++)
#pragma unroll
        for (int j = 0; j < 4; j++) acc[i][j] = 0ull;

#pragma unroll 4
    for (int k = 0; k < KDIM; k++) {
        ulonglong2 b01 = *(const ulonglong2*)(sW + k * NDIM + 8 * tx);
        ulonglong2 b23 = *(const ulonglong2*)(sW + k * NDIM + 8 * tx + 4);
#pragma unroll
        for (int i = 0; i < 4; i++) {
            unsigned long long pa = pack2(sA[(4 * ty + i) * PITCH + k]);
            acc[i][0] = ffma2(pa, b01.x, acc[i][0]);
            acc[i][1] = ffma2(pa, b01.y, acc[i][1]);
            acc[i][2] = ffma2(pa, b23.x, acc[i][2]);
            acc[i][3] = ffma2(pa, b23.y, acc[i][3]);
        }
    }

#pragma unroll
    for (int i = 0; i < 4; i++) {
        int row = rowbase + 4 * ty + i;
        if (row < M) {
            uint4 u;
            u.x = f2_to_h2(acc[i][0]);
            u.y = f2_to_h2(acc[i][1]);
            u.z = f2_to_h2(acc[i][2]);
            u.w = f2_to_h2(acc[i][3]);
            *(uint4*)(C + (size_t)row * NDIM + 8 * tx) = u;
        }
    }
}

// ---------------- CSR aggregation (fp16 gathers, fp32 accumulate) -----------
// out[i] = bias + dinv_i^2*feat[i] + sum_j norm_ij*feat[src_j]
// one warp per node; V4 = CH/8 lanes per edge-group (uint4 = 8 halfs each);
// EP = 32/V4 edges per iteration; shfl-tree cross-group reduce.
template<int CH, bool ZERO_DEG>
__global__ void aggregate_kernel(const __half* __restrict__ feat,
                                 const float* __restrict__ bias,
                                 float* __restrict__ out) {
    constexpr int V4 = CH / 8;       // 8 (CH=64) or 5 (CH=40)
    constexpr int EP = 32 / V4;      // 4 or 6
    int node = (blockIdx.x * blockDim.x + threadIdx.x) >> 5;
    if (node >= N_NODES) return;
    int lane = threadIdx.x & 31;
    int eg = lane / V4;              // edge group
    int c  = lane - eg * V4;         // uint4 index within row
    bool act = eg < EP;

    if (ZERO_DEG && lane == 0) g_deg[node] = 0;   // restore invariant for next call

    const int beg = g_off[node];
    const int end = g_off[node + 1];

    float acc[8];
#pragma unroll
    for (int j = 0; j < 8; j++) acc[j] = 0.f;

    if (eg == 0) {                   // self-loop + bias in group 0 only
        float dv = g_dinv[node];
        float s  = dv * dv;
        uint4 f = ((const uint4*)(feat + (size_t)node * CH))[c];
        float ff[8]; h8_to_f8(f, ff);
        float4 b0 = ((const float4*)bias)[2 * c];
        float4 b1 = ((const float4*)bias)[2 * c + 1];
        acc[0] = fmaf(s, ff[0], b0.x); acc[1] = fmaf(s, ff[1], b0.y);
        acc[2] = fmaf(s, ff[2], b0.z); acc[3] = fmaf(s, ff[3], b0.w);
        acc[4] = fmaf(s, ff[4], b1.x); acc[5] = fmaf(s, ff[5], b1.y);
        acc[6] = fmaf(s, ff[6], b1.z); acc[7] = fmaf(s, ff[7], b1.w);
    }

    // software-pipelined edge loop; dummy entries carry norm=0 (src=0 safe)
    int2 p = make_int2(0, 0);
    if (act && beg + eg < end) p = g_adj[beg + eg];
    for (int k = beg; k < end; k += EP) {
        int kn = k + EP;
        int2 pn = make_int2(0, 0);
        if (act && kn + eg < end) pn = g_adj[kn + eg];
        float nrm = __int_as_float(p.y);
        uint4 v = ((const uint4*)(feat + (size_t)p.x * CH))[c];
        float ff[8]; h8_to_f8(v, ff);
#pragma unroll
        for (int j = 0; j < 8; j++) acc[j] = fmaf(nrm, ff[j], acc[j]);
        p = pn;
    }

    // cross-group reduce into group 0 (pollution only reaches groups never read)
    const unsigned m = 0xffffffffu;
    if (EP == 4) {
#pragma unroll
        for (int j = 0; j < 8; j++) acc[j] += __shfl_down_sync(m, acc[j], 2 * V4);
#pragma unroll
        for (int j = 0; j < 8; j++) acc[j] += __shfl_down_sync(m, acc[j], V4);
    } else {  // EP == 6: g0+=g3,g1+=g4,g2+=g5 ; then guarded g0+=g2 ; g0+=g1
#pragma unroll
        for (int j = 0; j < 8; j++) acc[j] += __shfl_down_sync(m, acc[j], 3 * V4);
#pragma unroll
        for (int j = 0; j < 8; j++) {
            float t = __shfl_down_sync(m, acc[j], 2 * V4);
            if (eg == 0) acc[j] += t;
        }
#pragma unroll
        for (int j = 0; j < 8; j++) {
            float t = __shfl_down_sync(m, acc[j], V4);
            if (eg == 0) acc[j] += t;
        }
    }

    if (eg == 0) {
        float4* po = (float4*)(out + (size_t)node * CH);
        po[2 * c]     = make_float4(acc[0], acc[1], acc[2], acc[3]);
        po[2 * c + 1] = make_float4(acc[4], acc[5], acc[6], acc[7]);
    }
}

// ---------------- launch ----------------------------------------------------
extern "C" void kernel_launch(void* const* d_in, const int* in_sizes, int n_in,
                              void* d_out, int out_size) {
    const float* x  = (const float*)d_in[0];
    const int*   ei = (const int*)d_in[1];      // int32 words of edge_index (either dtype)
    const float* W1 = (const float*)d_in[2];
    const float* b1 = (const float*)d_in[3];
    const float* W2 = (const float*)d_in[4];
    const float* b2 = (const float*)d_in[5];
    float*       out = (float*)d_out;

    void *hw_p, *agg1_p, *h2w_p;
    cudaGetSymbolAddress(&hw_p,   g_hw);
    cudaGetSymbolAddress(&agg1_p, g_agg1);
    cudaGetSymbolAddress(&h2w_p,  g_h2w);

    constexpr int TPB = 256;

    // 1) detect index dtype (g_deg already zero: module init / prior agg2)
    detect_kernel<<<1, 128>>>(ei);
    // 2) degree histogram
    deg_kernel<<<NB_EDGE4, 256>>>(ei);
    // 3) per-block degree sums
    scanA_kernel<<<SCAN_NB, SCAN_TPB>>>();
    // 4) gemm1 (independent; placed here so ncu's window captures it)
    constexpr int SMEM1 = (128 * (IN_CH + 4) + IN_CH * HIDDEN) * sizeof(float); // 100352
    cudaFuncSetAttribute(gemm1_kernel, cudaFuncAttributeMaxDynamicSharedMemorySize, SMEM1);
    gemm1_kernel<<<(N_NODES + 127) / 128, 256, SMEM1>>>(x, W1, (__half*)hw_p, N_NODES);
    // 5) full scan -> off/cur/dinv
    scanC_kernel<<<SCAN_NB, SCAN_TPB>>>();
    // 6) counting sort into dst-grouped adjacency
    fill_kernel<<<NB_EDGE4, 256>>>(ei);

    // 7) layer1 aggregation (+bias,+self)
    const int nb_warps = (N_NODES * 32 + TPB - 1) / TPB;  // 1 warp per node
    aggregate_kernel<HIDDEN, false><<<nb_warps, TPB>>>((const __half*)hw_p, b1, (float*)agg1_p);

    // 8) gemm2 (relu fused into A-load)
    constexpr int SMEM2 = (128 * (HIDDEN + 4) + HIDDEN * NCLS) * sizeof(float); // 45056
    cudaFuncSetAttribute(gemm2_kernel, cudaFuncAttributeMaxDynamicSharedMemorySize, SMEM2);
    gemm2_kernel<<<(N_NODES + 127) / 128, 160, SMEM2>>>((const float*)agg1_p, W2,
                                                        (__half*)h2w_p, N_NODES);

    // 9) layer2 aggregation -> output (also re-zeroes g_deg for next call)
    aggregate_kernel<NCLS, true><<<nb_warps, TPB>>>((const __half*)h2w_p, b2, out);
}

// round 10
// speedup vs baseline: 1.4812x; 1.3365x over previous
#include <cuda_runtime.h>
#include <cuda_fp16.h>
#include <cstdint>

#define N_NODES 100000
#define N_EDGES 1600000
#define IN_CH   128
#define HIDDEN  64
#define NCLS    40

// ---------------- scratch (device globals; no allocation allowed) ----------
__device__ int   g_is64;
__device__ int   g_deg[N_NODES];       // zero-initialized at load; re-zeroed by agg2 tail
__device__ int   g_off[N_NODES + 1];
__device__ int   g_cur[N_NODES];
__device__ float g_dinv[N_NODES];
__device__ int   g_bsum[128];
__device__ int2  g_adj[N_EDGES];                     // (src, norm-as-bits), grouped by dst
__device__ __align__(16) __half g_hw [(size_t)N_NODES * HIDDEN];  // X @ W1 (fp16)
__device__ float g_agg1[(size_t)N_NODES * HIDDEN];                // layer1 agg (fp32)
__device__ __align__(16) __half g_h2w[(size_t)N_NODES * NCLS];    // relu(agg1) @ W2 (fp16)

// ---------------- packed f32x2 helpers --------------------------------------
__device__ __forceinline__ unsigned long long ffma2(unsigned long long a,
                                                    unsigned long long b,
                                                    unsigned long long c) {
    unsigned long long d;
    asm("fma.rn.f32x2 %0, %1, %2, %3;" : "=l"(d) : "l"(a), "l"(b), "l"(c));
    return d;
}
__device__ __forceinline__ unsigned long long pack2(float a) {
    unsigned long long d;
    asm("mov.b64 %0, {%1, %1};" : "=l"(d) : "f"(a));
    return d;
}
// 8 halfs (uint4) -> 8 floats
__device__ __forceinline__ void h8_to_f8(uint4 v, float* f) {
    float2 t;
    t = __half22float2(*(__half2*)&v.x); f[0] = t.x; f[1] = t.y;
    t = __half22float2(*(__half2*)&v.y); f[2] = t.x; f[3] = t.y;
    t = __half22float2(*(__half2*)&v.z); f[4] = t.x; f[5] = t.y;
    t = __half22float2(*(__half2*)&v.w); f[6] = t.x; f[7] = t.y;
}
// one f32x2 accumulator (2 floats) -> half2 bits
__device__ __forceinline__ unsigned f2_to_h2(unsigned long long a) {
    float2 f = *(float2*)&a;
    __half2 h = __float22half2_rn(f);
    return *(unsigned*)&h;
}
__device__ __forceinline__ unsigned pack_h2(float a, float b) {
    __half2 h = __float22half2_rn(make_float2(a, b));
    return *(unsigned*)&h;
}

// ---------------- detect index dtype ----------------------------------------
// int64 indices (<2^31) have zero high words at every odd int32 position.
__global__ void detect_kernel(const int* __restrict__ w) {
    __shared__ int acc;
    if (threadIdx.x == 0) acc = 0;
    __syncthreads();
    int v = 0;
    for (int j = threadIdx.x; j < 4096; j += blockDim.x) v |= w[2 * j + 1];
    atomicOr(&acc, v);
    __syncthreads();
    if (threadIdx.x == 0) g_is64 = (acc == 0) ? 1 : 0;
}

#define NB_EDGE4 1563                    // ceil(1.6M / (256*4))
#define EDGE4_T  (NB_EDGE4 * 256)

// g_deg is zero on entry (module init / previous call's agg2 tail)
__global__ void deg_kernel(const int* __restrict__ w) {
    int idx = blockIdx.x * 256 + threadIdx.x;
    int is64 = g_is64;
#pragma unroll
    for (int j = 0; j < 4; j++) {
        int e = idx + j * EDGE4_T;
        if (e < N_EDGES) {
            int d = is64 ? w[2 * (N_EDGES + e)] : w[N_EDGES + e];
            if ((unsigned)d >= N_NODES) d = 0;
            atomicAdd(&g_deg[d], 1);
        }
    }
}

// ---------------- scan: A = per-block sums; C = full scan ------------------
#define SCAN_NB  128
#define SCAN_TPB 256
#define SCAN_PER 4        // 128*256*4 = 131072 >= N_NODES

__global__ void scanA_kernel() {
    __shared__ int red[SCAN_TPB];
    int t = threadIdx.x;
    int base = (blockIdx.x * SCAN_TPB + t) * SCAN_PER;
    int s = 0;
#pragma unroll
    for (int j = 0; j < SCAN_PER; j++) {
        int i = base + j;
        if (i < N_NODES) s += g_deg[i];
    }
    red[t] = s;
    __syncthreads();
    for (int o = SCAN_TPB / 2; o > 0; o >>= 1) {
        if (t < o) red[t] += red[t + o];
        __syncthreads();
    }
    if (t == 0) g_bsum[blockIdx.x] = red[0];
}

__global__ void scanC_kernel() {
    __shared__ int top[SCAN_NB];
    __shared__ int p[SCAN_TPB];
    int t = threadIdx.x;

    if (t < SCAN_NB) top[t] = g_bsum[t];
    __syncthreads();
    for (int o = 1; o < SCAN_NB; o <<= 1) {
        int v = (t >= o && t < SCAN_NB) ? top[t - o] : 0;
        __syncthreads();
        if (t < SCAN_NB) top[t] += v;
        __syncthreads();
    }
    int bpre = (blockIdx.x > 0) ? top[blockIdx.x - 1] : 0;
    if (blockIdx.x == SCAN_NB - 1 && t == 0) g_off[N_NODES] = top[SCAN_NB - 1];

    int base = (blockIdx.x * SCAN_TPB + t) * SCAN_PER;
    int loc[SCAN_PER];
    int s = 0;
#pragma unroll
    for (int j = 0; j < SCAN_PER; j++) {
        int i = base + j;
        int d = (i < N_NODES) ? g_deg[i] : 0;
        loc[j] = s;
        s += d;
    }
    p[t] = s;
    __syncthreads();
    for (int o = 1; o < SCAN_TPB; o <<= 1) {
        int v = (t >= o) ? p[t - o] : 0;
        __syncthreads();
        p[t] += v;
        __syncthreads();
    }
    int pre = bpre + ((t > 0) ? p[t - 1] : 0);
#pragma unroll
    for (int j = 0; j < SCAN_PER; j++) {
        int i = base + j;
        if (i < N_NODES) {
            int o = pre + loc[j];
            g_off[i] = o;
            g_cur[i] = o;
            g_dinv[i] = rsqrtf((float)(g_deg[i] + 1));  // +1 self loop
        }
    }
}

// counting-sort edges by dst into g_adj (re-decodes ei; norm precomputed)
__global__ void fill_kernel(const int* __restrict__ w) {
    int idx = blockIdx.x * 256 + threadIdx.x;
    int is64 = g_is64;
#pragma unroll
    for (int j = 0; j < 4; j++) {
        int e = idx + j * EDGE4_T;
        if (e < N_EDGES) {
            int s, d;
            if (is64) { s = w[2 * e]; d = w[2 * (N_EDGES + e)]; }
            else      { s = w[e];     d = w[N_EDGES + e]; }
            if ((unsigned)s >= N_NODES) s = 0;
            if ((unsigned)d >= N_NODES) d = 0;
            int pos = atomicAdd(&g_cur[d], 1);
            g_adj[pos] = make_int2(s, __float_as_int(g_dinv[s] * g_dinv[d]));
        }
    }
}

// ---------------- GEMM1 (tensor core): fp16 C[M,64] = A[M,128]*W[128,64] ----
// mma.sync.m16n8k16 f32.f16.f16.f32; 256 thr = 8 warps, warp owns 16 rows x 64 cols.
#define SA_PITCH 136   // halfs per A smem row (128 + 8 pad -> ldmatrix conflict-free)
#define SW_PITCH 72    // halfs per W smem row (64 + 8 pad)

__global__ void gemm1_kernel(const float* __restrict__ A,
                             const float* __restrict__ W,
                             __half* __restrict__ C, int M) {
    extern __shared__ __half sh[];
    __half* sA = sh;                       // [128][SA_PITCH]
    __half* sW = sh + 128 * SA_PITCH;      // [128][SW_PITCH]
    const int tid = threadIdx.x;
    const int rowbase = blockIdx.x * 128;

    // load + convert A tile (128 x 128 fp32 -> fp16)
    for (int i = tid; i < 128 * 32; i += 256) {
        int r  = i >> 5;
        int c4 = (i & 31) * 4;
        int row = rowbase + r;
        float4 a = make_float4(0.f, 0.f, 0.f, 0.f);
        if (row < M) a = *(const float4*)(A + (size_t)row * IN_CH + c4);
        uint2 u = make_uint2(pack_h2(a.x, a.y), pack_h2(a.z, a.w));
        *(uint2*)(sA + r * SA_PITCH + c4) = u;
    }
    // load + convert W (128 x 64 fp32 -> fp16)
    for (int i = tid; i < 128 * 16; i += 256) {
        int r  = i >> 4;
        int c4 = (i & 15) * 4;
        float4 a = *(const float4*)(W + r * HIDDEN + c4);
        uint2 u = make_uint2(pack_h2(a.x, a.y), pack_h2(a.z, a.w));
        *(uint2*)(sW + r * SW_PITCH + c4) = u;
    }
    __syncthreads();

    const int warp = tid >> 5, lane = tid & 31;
    const int lr  = lane & 7;        // row within 8x8 tile
    const int seg = lane >> 3;       // which of the 4 ldmatrix submatrices

    // A x4 lane address parts: tiles (rows0-7,k0-7),(rows8-15,k0-7),(rows0-7,k8-15),(rows8-15,k8-15)
    const int a_row  = warp * 16 + (seg & 1) * 8 + lr;
    const int a_koff = (seg >> 1) * 8;
    // B x4.trans lane address parts: (k0-7,t),(k8-15,t),(k0-7,t+1),(k8-15,t+1)
    const int b_kr   = (seg & 1) * 8 + lr;
    const int b_toff = (seg >> 1);

    float acc[8][4];
#pragma unroll
    for (int t = 0; t < 8; t++)
#pragma unroll
        for (int j = 0; j < 4; j++) acc[t][j] = 0.f;

#pragma unroll
    for (int s = 0; s < 8; s++) {          // k-steps of 16
        unsigned a0, a1, a2, a3;
        {
            unsigned ad = (unsigned)__cvta_generic_to_shared(
                sA + a_row * SA_PITCH + s * 16 + a_koff);
            asm volatile("ldmatrix.sync.aligned.m8n8.x4.shared.b16 {%0,%1,%2,%3}, [%4];"
                         : "=r"(a0), "=r"(a1), "=r"(a2), "=r"(a3) : "r"(ad));
        }
        unsigned b[8][2];
#pragma unroll
        for (int tp = 0; tp < 4; tp++) {   // n-tile pairs (2tp, 2tp+1)
            unsigned bd = (unsigned)__cvta_generic_to_shared(
                sW + (s * 16 + b_kr) * SW_PITCH + (2 * tp + b_toff) * 8);
            unsigned r0, r1, r2, r3;
            asm volatile("ldmatrix.sync.aligned.m8n8.x4.trans.shared.b16 {%0,%1,%2,%3}, [%4];"
                         : "=r"(r0), "=r"(r1), "=r"(r2), "=r"(r3) : "r"(bd));
            b[2 * tp][0] = r0; b[2 * tp][1] = r1;
            b[2 * tp + 1][0] = r2; b[2 * tp + 1][1] = r3;
        }
#pragma unroll
        for (int t = 0; t < 8; t++) {
            asm volatile(
                "mma.sync.aligned.m16n8k16.row.col.f32.f16.f16.f32 "
                "{%0,%1,%2,%3}, {%4,%5,%6,%7}, {%8,%9}, {%0,%1,%2,%3};"
                : "+f"(acc[t][0]), "+f"(acc[t][1]), "+f"(acc[t][2]), "+f"(acc[t][3])
                : "r"(a0), "r"(a1), "r"(a2), "r"(a3), "r"(b[t][0]), "r"(b[t][1]));
        }
    }

    // store: lane holds rows (m0, m0+8), cols (2q, 2q+1) per tile
    const int m0 = rowbase + warp * 16 + (lane >> 2);
    const int cb = (lane & 3) * 2;
#pragma unroll
    for (int t = 0; t < 8; t++) {
        int col = t * 8 + cb;
        if (m0 < M)
            *(unsigned*)(C + (size_t)m0 * HIDDEN + col) = pack_h2(acc[t][0], acc[t][1]);
        if (m0 + 8 < M)
            *(unsigned*)(C + (size_t)(m0 + 8) * HIDDEN + col) = pack_h2(acc[t][2], acc[t][3]);
    }
}

// ---------------- GEMM2: fp16 C[M,40] = relu(A[M,64]) * W[64,40] -----------
__global__ void gemm2_kernel(const float* __restrict__ A,
                             const float* __restrict__ W,
                             __half* __restrict__ C, int M) {
    constexpr int KDIM = HIDDEN, NDIM = NCLS, ROWS = 128;
    constexpr int TX = NDIM / 8, TY = ROWS / 4, NT = TX * TY;  // 5 x 32 = 160
    constexpr int PITCH = KDIM + 4;
    extern __shared__ float smem[];
    float* sA = smem;
    float* sW = smem + ROWS * PITCH;

    const int tid     = threadIdx.x;
    const int rowbase = blockIdx.x * ROWS;

    for (int v = tid; v < KDIM * NDIM / 4; v += NT)
        ((float4*)sW)[v] = ((const float4*)W)[v];

    constexpr int KC4 = KDIM / 4;
    for (int v = tid; v < ROWS * KC4; v += NT) {
        int r  = v / KC4;
        int kc = (v - r * KC4) * 4;
        int row = rowbase + r;
        float4 a = make_float4(0.f, 0.f, 0.f, 0.f);
        if (row < M) a = *(const float4*)(A + (size_t)row * KDIM + kc);
        a.x = fmaxf(a.x, 0.f); a.y = fmaxf(a.y, 0.f);
        a.z = fmaxf(a.z, 0.f); a.w = fmaxf(a.w, 0.f);
        *(float4*)(sA + r * PITCH + kc) = a;
    }
    __syncthreads();

    const int ty = tid / TX, tx = tid - (tid / TX) * TX;
    unsigned long long acc[4][4];
#pragma unroll
    for (int i = 0; i < 4; i++)
#pragma unroll
        for (int j = 0; j < 4; j++) acc[i][j] = 0ull;

#pragma unroll 4
    for (int k = 0; k < KDIM; k++) {
        ulonglong2 b01 = *(const ulonglong2*)(sW + k * NDIM + 8 * tx);
        ulonglong2 b23 = *(const ulonglong2*)(sW + k * NDIM + 8 * tx + 4);
#pragma unroll
        for (int i = 0; i < 4; i++) {
            unsigned long long pa = pack2(sA[(4 * ty + i) * PITCH + k]);
            acc[i][0] = ffma2(pa, b01.x, acc[i][0]);
            acc[i][1] = ffma2(pa, b01.y, acc[i][1]);
            acc[i][2] = ffma2(pa, b23.x, acc[i][2]);
            acc[i][3] = ffma2(pa, b23.y, acc[i][3]);
        }
    }

#pragma unroll
    for (int i = 0; i < 4; i++) {
        int row = rowbase + 4 * ty + i;
        if (row < M) {
            uint4 u;
            u.x = f2_to_h2(acc[i][0]);
            u.y = f2_to_h2(acc[i][1]);
            u.z = f2_to_h2(acc[i][2]);
            u.w = f2_to_h2(acc[i][3]);
            *(uint4*)(C + (size_t)row * NDIM + 8 * tx) = u;
        }
    }
}

// ---------------- CSR aggregation (fp16 gathers, fp32 accumulate) -----------
// out[i] = bias + dinv_i^2*feat[i] + sum_j norm_ij*feat[src_j]
// one warp per node; V4 = CH/8 lanes per edge-group (uint4 = 8 halfs each);
// EP = 32/V4 edges per iteration; shfl-tree cross-group reduce.
template<int CH, bool ZERO_DEG>
__global__ void aggregate_kernel(const __half* __restrict__ feat,
                                 const float* __restrict__ bias,
                                 float* __restrict__ out) {
    constexpr int V4 = CH / 8;       // 8 (CH=64) or 5 (CH=40)
    constexpr int EP = 32 / V4;      // 4 or 6
    int node = (blockIdx.x * blockDim.x + threadIdx.x) >> 5;
    if (node >= N_NODES) return;
    int lane = threadIdx.x & 31;
    int eg = lane / V4;              // edge group
    int c  = lane - eg * V4;         // uint4 index within row
    bool act = eg < EP;

    if (ZERO_DEG && lane == 0) g_deg[node] = 0;   // restore invariant for next call

    const int beg = g_off[node];
    const int end = g_off[node + 1];

    float acc[8];
#pragma unroll
    for (int j = 0; j < 8; j++) acc[j] = 0.f;

    if (eg == 0) {                   // self-loop + bias in group 0 only
        float dv = g_dinv[node];
        float s  = dv * dv;
        uint4 f = ((const uint4*)(feat + (size_t)node * CH))[c];
        float ff[8]; h8_to_f8(f, ff);
        float4 b0 = ((const float4*)bias)[2 * c];
        float4 b1 = ((const float4*)bias)[2 * c + 1];
        acc[0] = fmaf(s, ff[0], b0.x); acc[1] = fmaf(s, ff[1], b0.y);
        acc[2] = fmaf(s, ff[2], b0.z); acc[3] = fmaf(s, ff[3], b0.w);
        acc[4] = fmaf(s, ff[4], b1.x); acc[5] = fmaf(s, ff[5], b1.y);
        acc[6] = fmaf(s, ff[6], b1.z); acc[7] = fmaf(s, ff[7], b1.w);
    }

    // software-pipelined edge loop; dummy entries carry norm=0 (src=0 safe)
    int2 p = make_int2(0, 0);
    if (act && beg + eg < end) p = g_adj[beg + eg];
    for (int k = beg; k < end; k += EP) {
        int kn = k + EP;
        int2 pn = make_int2(0, 0);
        if (act && kn + eg < end) pn = g_adj[kn + eg];
        float nrm = __int_as_float(p.y);
        uint4 v = ((const uint4*)(feat + (size_t)p.x * CH))[c];
        float ff[8]; h8_to_f8(v, ff);
#pragma unroll
        for (int j = 0; j < 8; j++) acc[j] = fmaf(nrm, ff[j], acc[j]);
        p = pn;
    }

    // cross-group reduce into group 0 (pollution only reaches groups never read)
    const unsigned m = 0xffffffffu;
    if (EP == 4) {
#pragma unroll
        for (int j = 0; j < 8; j++) acc[j] += __shfl_down_sync(m, acc[j], 2 * V4);
#pragma unroll
        for (int j = 0; j < 8; j++) acc[j] += __shfl_down_sync(m, acc[j], V4);
    } else {  // EP == 6: g0+=g3,g1+=g4,g2+=g5 ; then guarded g0+=g2 ; g0+=g1
#pragma unroll
        for (int j = 0; j < 8; j++) acc[j] += __shfl_down_sync(m, acc[j], 3 * V4);
#pragma unroll
        for (int j = 0; j < 8; j++) {
            float t = __shfl_down_sync(m, acc[j], 2 * V4);
            if (eg == 0) acc[j] += t;
        }
#pragma unroll
        for (int j = 0; j < 8; j++) {
            float t = __shfl_down_sync(m, acc[j], V4);
            if (eg == 0) acc[j] += t;
        }
    }

    if (eg == 0) {
        float4* po = (float4*)(out + (size_t)node * CH);
        po[2 * c]     = make_float4(acc[0], acc[1], acc[2], acc[3]);
        po[2 * c + 1] = make_float4(acc[4], acc[5], acc[6], acc[7]);
    }
}

// ---------------- launch ----------------------------------------------------
extern "C" void kernel_launch(void* const* d_in, const int* in_sizes, int n_in,
                              void* d_out, int out_size) {
    const float* x  = (const float*)d_in[0];
    const int*   ei = (const int*)d_in[1];      // int32 words of edge_index (either dtype)
    const float* W1 = (const float*)d_in[2];
    const float* b1 = (const float*)d_in[3];
    const float* W2 = (const float*)d_in[4];
    const float* b2 = (const float*)d_in[5];
    float*       out = (float*)d_out;

    void *hw_p, *agg1_p, *h2w_p;
    cudaGetSymbolAddress(&hw_p,   g_hw);
    cudaGetSymbolAddress(&agg1_p, g_agg1);
    cudaGetSymbolAddress(&h2w_p,  g_h2w);

    constexpr int TPB = 256;

    // 1) detect index dtype (g_deg already zero: module init / prior agg2)
    detect_kernel<<<1, 128>>>(ei);
    // 2) degree histogram
    deg_kernel<<<NB_EDGE4, 256>>>(ei);
    // 3) per-block degree sums
    scanA_kernel<<<SCAN_NB, SCAN_TPB>>>();
    // 4) gemm1 via tensor cores (independent; ncu window lands here)
    constexpr int SMEM1 = (128 * SA_PITCH + 128 * SW_PITCH) * sizeof(__half); // 53248
    cudaFuncSetAttribute(gemm1_kernel, cudaFuncAttributeMaxDynamicSharedMemorySize, SMEM1);
    gemm1_kernel<<<(N_NODES + 127) / 128, 256, SMEM1>>>(x, W1, (__half*)hw_p, N_NODES);
    // 5) full scan -> off/cur/dinv
    scanC_kernel<<<SCAN_NB, SCAN_TPB>>>();
    // 6) counting sort into dst-grouped adjacency
    fill_kernel<<<NB_EDGE4, 256>>>(ei);

    // 7) layer1 aggregation (+bias,+self)
    const int nb_warps = (N_NODES * 32 + TPB - 1) / TPB;  // 1 warp per node
    aggregate_kernel<HIDDEN, false><<<nb_warps, TPB>>>((const __half*)hw_p, b1, (float*)agg1_p);

    // 8) gemm2 (relu fused into A-load)
    constexpr int SMEM2 = (128 * (HIDDEN + 4) + HIDDEN * NCLS) * sizeof(float); // 45056
    cudaFuncSetAttribute(gemm2_kernel, cudaFuncAttributeMaxDynamicSharedMemorySize, SMEM2);
    gemm2_kernel<<<(N_NODES + 127) / 128, 160, SMEM2>>>((const float*)agg1_p, W2,
                                                        (__half*)h2w_p, N_NODES);

    // 9) layer2 aggregation -> output (also re-zeroes g_deg for next call)
    aggregate_kernel<NCLS, true><<<nb_warps, TPB>>>((const __half*)h2w_p, b2, out);
}

// round 11
// speedup vs baseline: 1.5188x; 1.0254x over previous
#include <cuda_runtime.h>
#include <cuda_fp16.h>
#include <cstdint>

#define N_NODES 100000
#define N_EDGES 1600000
#define IN_CH   128
#define HIDDEN  64
#define NCLS    40

// ---------------- scratch (device globals; no allocation allowed) ----------
__device__ int   g_is64;
__device__ int   g_deg[N_NODES];       // zero at load; re-zeroed by agg2 tail
__device__ int   g_off[N_NODES + 1];
__device__ int   g_cur[N_NODES];
__device__ float g_dinv[N_NODES];
__device__ int   g_bsum[128];
__device__ unsigned g_adj[N_EDGES];    // (src<<15) | fp16(norm) sans sign, dst-grouped
__device__ __align__(16) __half g_hw [(size_t)N_NODES * HIDDEN];  // X @ W1 (fp16)
__device__ float g_agg1[(size_t)N_NODES * HIDDEN];                // layer1 agg (fp32)
__device__ __align__(16) __half g_h2w[(size_t)N_NODES * NCLS];    // relu(agg1)@W2 (fp16)

// ---------------- helpers ----------------------------------------------------
__device__ __forceinline__ unsigned long long ffma2(unsigned long long a,
                                                    unsigned long long b,
                                                    unsigned long long c) {
    unsigned long long d;
    asm("fma.rn.f32x2 %0, %1, %2, %3;" : "=l"(d) : "l"(a), "l"(b), "l"(c));
    return d;
}
__device__ __forceinline__ unsigned long long pack2(float a) {
    unsigned long long d;
    asm("mov.b64 %0, {%1, %1};" : "=l"(d) : "f"(a));
    return d;
}
__device__ __forceinline__ void h8_to_f8(uint4 v, float* f) {
    float2 t;
    t = __half22float2(*(__half2*)&v.x); f[0] = t.x; f[1] = t.y;
    t = __half22float2(*(__half2*)&v.y); f[2] = t.x; f[3] = t.y;
    t = __half22float2(*(__half2*)&v.z); f[4] = t.x; f[5] = t.y;
    t = __half22float2(*(__half2*)&v.w); f[6] = t.x; f[7] = t.y;
}
__device__ __forceinline__ unsigned f2_to_h2(unsigned long long a) {
    float2 f = *(float2*)&a;
    __half2 h = __float22half2_rn(f);
    return *(unsigned*)&h;
}
__device__ __forceinline__ unsigned pack_h2(float a, float b) {
    __half2 h = __float22half2_rn(make_float2(a, b));
    return *(unsigned*)&h;
}

// ---------------- detect index dtype ----------------------------------------
__global__ void detect_kernel(const int* __restrict__ w) {
    __shared__ int acc;
    if (threadIdx.x == 0) acc = 0;
    __syncthreads();
    int v = 0;
    for (int j = threadIdx.x; j < 4096; j += blockDim.x) v |= w[2 * j + 1];
    atomicOr(&acc, v);
    __syncthreads();
    if (threadIdx.x == 0) g_is64 = (acc == 0) ? 1 : 0;
}

#define NB_EDGE4 1563
#define EDGE4_T  (NB_EDGE4 * 256)

__global__ void deg_kernel(const int* __restrict__ w) {
    int idx = blockIdx.x * 256 + threadIdx.x;
    int is64 = g_is64;
#pragma unroll
    for (int j = 0; j < 4; j++) {
        int e = idx + j * EDGE4_T;
        if (e < N_EDGES) {
            int d = is64 ? w[2 * (N_EDGES + e)] : w[N_EDGES + e];
            if ((unsigned)d >= N_NODES) d = 0;
            atomicAdd(&g_deg[d], 1);
        }
    }
}

// ---------------- scan ------------------------------------------------------
#define SCAN_NB  128
#define SCAN_TPB 256
#define SCAN_PER 4

__global__ void scanA_kernel() {
    __shared__ int red[SCAN_TPB];
    int t = threadIdx.x;
    int base = (blockIdx.x * SCAN_TPB + t) * SCAN_PER;
    int s = 0;
#pragma unroll
    for (int j = 0; j < SCAN_PER; j++) {
        int i = base + j;
        if (i < N_NODES) s += g_deg[i];
    }
    red[t] = s;
    __syncthreads();
    for (int o = SCAN_TPB / 2; o > 0; o >>= 1) {
        if (t < o) red[t] += red[t + o];
        __syncthreads();
    }
    if (t == 0) g_bsum[blockIdx.x] = red[0];
}

__global__ void scanC_kernel() {
    __shared__ int top[SCAN_NB];
    __shared__ int p[SCAN_TPB];
    int t = threadIdx.x;

    if (t < SCAN_NB) top[t] = g_bsum[t];
    __syncthreads();
    for (int o = 1; o < SCAN_NB; o <<= 1) {
        int v = (t >= o && t < SCAN_NB) ? top[t - o] : 0;
        __syncthreads();
        if (t < SCAN_NB) top[t] += v;
        __syncthreads();
    }
    int bpre = (blockIdx.x > 0) ? top[blockIdx.x - 1] : 0;
    if (blockIdx.x == SCAN_NB - 1 && t == 0) g_off[N_NODES] = top[SCAN_NB - 1];

    int base = (blockIdx.x * SCAN_TPB + t) * SCAN_PER;
    int loc[SCAN_PER];
    int s = 0;
#pragma unroll
    for (int j = 0; j < SCAN_PER; j++) {
        int i = base + j;
        int d = (i < N_NODES) ? g_deg[i] : 0;
        loc[j] = s;
        s += d;
    }
    p[t] = s;
    __syncthreads();
    for (int o = 1; o < SCAN_TPB; o <<= 1) {
        int v = (t >= o) ? p[t - o] : 0;
        __syncthreads();
        p[t] += v;
        __syncthreads();
    }
    int pre = bpre + ((t > 0) ? p[t - 1] : 0);
#pragma unroll
    for (int j = 0; j < SCAN_PER; j++) {
        int i = base + j;
        if (i < N_NODES) {
            int o = pre + loc[j];
            g_off[i] = o;
            g_cur[i] = o;
            g_dinv[i] = rsqrtf((float)(g_deg[i] + 1));  // +1 self loop
        }
    }
}

// counting-sort edges by dst; packed entry = (src<<15) | fp16(norm) [sign=0]
__global__ void fill_kernel(const int* __restrict__ w) {
    int idx = blockIdx.x * 256 + threadIdx.x;
    int is64 = g_is64;
#pragma unroll
    for (int j = 0; j < 4; j++) {
        int e = idx + j * EDGE4_T;
        if (e < N_EDGES) {
            int s, d;
            if (is64) { s = w[2 * e]; d = w[2 * (N_EDGES + e)]; }
            else      { s = w[e];     d = w[N_EDGES + e]; }
            if ((unsigned)s >= N_NODES) s = 0;
            if ((unsigned)d >= N_NODES) d = 0;
            int pos = atomicAdd(&g_cur[d], 1);
            __half h = __float2half_rn(g_dinv[s] * g_dinv[d]);   // in (0,1]: sign bit 0
            g_adj[pos] = ((unsigned)s << 15) | (unsigned)__half_as_ushort(h);
        }
    }
}

// ---------------- GEMM1 (tensor core, A direct from gmem) -------------------
// fp16 C[M,64] = A[M,128] * W[128,64]; 256 thr = 8 warps x 16 rows.
// A fragments built in registers (float2 LDG + cvt); B via smem ldmatrix.trans.
#define SW_PITCH 72    // halfs per W smem row (64 + 8 pad)

__global__ __launch_bounds__(256) void gemm1_kernel(const float* __restrict__ A,
                                                    const float* __restrict__ W,
                                                    __half* __restrict__ C, int M) {
    __shared__ __half sW[128 * SW_PITCH];  // 18432 B
    const int tid = threadIdx.x;

    // load + convert W (128 x 64 fp32 -> fp16)
    for (int i = tid; i < 128 * 16; i += 256) {
        int r  = i >> 4;
        int c4 = (i & 15) * 4;
        float4 a = *(const float4*)(W + r * HIDDEN + c4);
        *(uint2*)(sW + r * SW_PITCH + c4) = make_uint2(pack_h2(a.x, a.y), pack_h2(a.z, a.w));
    }
    __syncthreads();

    const int warp = tid >> 5, lane = tid & 31;
    const int r0 = blockIdx.x * 128 + warp * 16 + (lane >> 2);
    const int r1 = r0 + 8;
    // clamp OOB rows to row 0 (harmless: their results are masked at store)
    const float* pA0 = A + (size_t)(r0 < M ? r0 : 0) * IN_CH + (lane & 3) * 2;
    const float* pA1 = A + (size_t)(r1 < M ? r1 : 0) * IN_CH + (lane & 3) * 2;

    const int lr  = lane & 7;
    const int seg = lane >> 3;
    const int b_kr   = (seg & 1) * 8 + lr;
    const int b_toff = (seg >> 1);

    float acc[8][4];
#pragma unroll
    for (int t = 0; t < 8; t++)
#pragma unroll
        for (int j = 0; j < 4; j++) acc[t][j] = 0.f;

#pragma unroll
    for (int s = 0; s < 8; s++) {          // k-steps of 16
        float2 f;
        unsigned a0, a1, a2, a3;
        f = *(const float2*)(pA0 + s * 16);     a0 = pack_h2(f.x, f.y);
        f = *(const float2*)(pA1 + s * 16);     a1 = pack_h2(f.x, f.y);
        f = *(const float2*)(pA0 + s * 16 + 8); a2 = pack_h2(f.x, f.y);
        f = *(const float2*)(pA1 + s * 16 + 8); a3 = pack_h2(f.x, f.y);

        unsigned b[8][2];
#pragma unroll
        for (int tp = 0; tp < 4; tp++) {
            unsigned bd = (unsigned)__cvta_generic_to_shared(
                sW + (s * 16 + b_kr) * SW_PITCH + (2 * tp + b_toff) * 8);
            unsigned q0, q1, q2, q3;
            asm volatile("ldmatrix.sync.aligned.m8n8.x4.trans.shared.b16 {%0,%1,%2,%3}, [%4];"
                         : "=r"(q0), "=r"(q1), "=r"(q2), "=r"(q3) : "r"(bd));
            b[2 * tp][0] = q0; b[2 * tp][1] = q1;
            b[2 * tp + 1][0] = q2; b[2 * tp + 1][1] = q3;
        }
#pragma unroll
        for (int t = 0; t < 8; t++) {
            asm volatile(
                "mma.sync.aligned.m16n8k16.row.col.f32.f16.f16.f32 "
                "{%0,%1,%2,%3}, {%4,%5,%6,%7}, {%8,%9}, {%0,%1,%2,%3};"
                : "+f"(acc[t][0]), "+f"(acc[t][1]), "+f"(acc[t][2]), "+f"(acc[t][3])
                : "r"(a0), "r"(a1), "r"(a2), "r"(a3), "r"(b[t][0]), "r"(b[t][1]));
        }
    }

    const int cb = (lane & 3) * 2;
#pragma unroll
    for (int t = 0; t < 8; t++) {
        int col = t * 8 + cb;
        if (r0 < M)
            *(unsigned*)(C + (size_t)r0 * HIDDEN + col) = pack_h2(acc[t][0], acc[t][1]);
        if (r1 < M)
            *(unsigned*)(C + (size_t)r1 * HIDDEN + col) = pack_h2(acc[t][2], acc[t][3]);
    }
}

// ---------------- GEMM2: fp16 C[M,40] = relu(A[M,64]) * W[64,40] -----------
__global__ void gemm2_kernel(const float* __restrict__ A,
                             const float* __restrict__ W,
                             __half* __restrict__ C, int M) {
    constexpr int KDIM = HIDDEN, NDIM = NCLS, ROWS = 128;
    constexpr int TX = NDIM / 8, TY = ROWS / 4, NT = TX * TY;  // 5 x 32 = 160
    constexpr int PITCH = KDIM + 4;
    extern __shared__ float smem[];
    float* sA = smem;
    float* sW = smem + ROWS * PITCH;

    const int tid     = threadIdx.x;
    const int rowbase = blockIdx.x * ROWS;

    for (int v = tid; v < KDIM * NDIM / 4; v += NT)
        ((float4*)sW)[v] = ((const float4*)W)[v];

    constexpr int KC4 = KDIM / 4;
    for (int v = tid; v < ROWS * KC4; v += NT) {
        int r  = v / KC4;
        int kc = (v - r * KC4) * 4;
        int row = rowbase + r;
        float4 a = make_float4(0.f, 0.f, 0.f, 0.f);
        if (row < M) a = *(const float4*)(A + (size_t)row * KDIM + kc);
        a.x = fmaxf(a.x, 0.f); a.y = fmaxf(a.y, 0.f);
        a.z = fmaxf(a.z, 0.f); a.w = fmaxf(a.w, 0.f);
        *(float4*)(sA + r * PITCH + kc) = a;
    }
    __syncthreads();

    const int ty = tid / TX, tx = tid - (tid / TX) * TX;
    unsigned long long acc[4][4];
#pragma unroll
    for (int i = 0; i < 4; i++)
#pragma unroll
        for (int j = 0; j < 4; j++) acc[i][j] = 0ull;

#pragma unroll 4
    for (int k = 0; k < KDIM; k++) {
        ulonglong2 b01 = *(const ulonglong2*)(sW + k * NDIM + 8 * tx);
        ulonglong2 b23 = *(const ulonglong2*)(sW + k * NDIM + 8 * tx + 4);
#pragma unroll
        for (int i = 0; i < 4; i++) {
            unsigned long long pa = pack2(sA[(4 * ty + i) * PITCH + k]);
            acc[i][0] = ffma2(pa, b01.x, acc[i][0]);
            acc[i][1] = ffma2(pa, b01.y, acc[i][1]);
            acc[i][2] = ffma2(pa, b23.x, acc[i][2]);
            acc[i][3] = ffma2(pa, b23.y, acc[i][3]);
        }
    }

#pragma unroll
    for (int i = 0; i < 4; i++) {
        int row = rowbase + 4 * ty + i;
        if (row < M) {
            uint4 u;
            u.x = f2_to_h2(acc[i][0]);
            u.y = f2_to_h2(acc[i][1]);
            u.z = f2_to_h2(acc[i][2]);
            u.w = f2_to_h2(acc[i][3]);
            *(uint4*)(C + (size_t)row * NDIM + 8 * tx) = u;
        }
    }
}

// ---------------- CSR aggregation (fp16 gathers, fp32 accumulate) -----------
// adj entry: (src<<15)|fp16(norm); dummy 0 -> src 0, norm 0 (safe).
template<int CH, bool ZERO_DEG>
__global__ void aggregate_kernel(const __half* __restrict__ feat,
                                 const float* __restrict__ bias,
                                 float* __restrict__ out) {
    constexpr int V4 = CH / 8;       // 8 (CH=64) or 5 (CH=40)
    constexpr int EP = 32 / V4;      // 4 or 6
    int node = (blockIdx.x * blockDim.x + threadIdx.x) >> 5;
    if (node >= N_NODES) return;
    int lane = threadIdx.x & 31;
    int eg = lane / V4;
    int c  = lane - eg * V4;
    bool act = eg < EP;

    if (ZERO_DEG && lane == 0) g_deg[node] = 0;

    const int beg = g_off[node];
    const int end = g_off[node + 1];

    float acc[8];
#pragma unroll
    for (int j = 0; j < 8; j++) acc[j] = 0.f;

    if (eg == 0) {                   // self-loop + bias in group 0 only
        float dv = g_dinv[node];
        float s  = dv * dv;
        uint4 f = ((const uint4*)(feat + (size_t)node * CH))[c];
        float ff[8]; h8_to_f8(f, ff);
        float4 b0 = ((const float4*)bias)[2 * c];
        float4 b1 = ((const float4*)bias)[2 * c + 1];
        acc[0] = fmaf(s, ff[0], b0.x); acc[1] = fmaf(s, ff[1], b0.y);
        acc[2] = fmaf(s, ff[2], b0.z); acc[3] = fmaf(s, ff[3], b0.w);
        acc[4] = fmaf(s, ff[4], b1.x); acc[5] = fmaf(s, ff[5], b1.y);
        acc[6] = fmaf(s, ff[6], b1.z); acc[7] = fmaf(s, ff[7], b1.w);
    }

    unsigned p = 0u;
    if (act && beg + eg < end) p = g_adj[beg + eg];
    for (int k = beg; k < end; k += EP) {
        int kn = k + EP;
        unsigned pn = 0u;
        if (act && kn + eg < end) pn = g_adj[kn + eg];
        int   src = (int)(p >> 15);
        float nrm = __half2float(__ushort_as_half((unsigned short)(p & 0x7FFFu)));
        uint4 v = ((const uint4*)(feat + (size_t)src * CH))[c];
        float ff[8]; h8_to_f8(v, ff);
#pragma unroll
        for (int j = 0; j < 8; j++) acc[j] = fmaf(nrm, ff[j], acc[j]);
        p = pn;
    }

    const unsigned m = 0xffffffffu;
    if (EP == 4) {
#pragma unroll
        for (int j = 0; j < 8; j++) acc[j] += __shfl_down_sync(m, acc[j], 2 * V4);
#pragma unroll
        for (int j = 0; j < 8; j++) acc[j] += __shfl_down_sync(m, acc[j], V4);
    } else {  // EP == 6
#pragma unroll
        for (int j = 0; j < 8; j++) acc[j] += __shfl_down_sync(m, acc[j], 3 * V4);
#pragma unroll
        for (int j = 0; j < 8; j++) {
            float t = __shfl_down_sync(m, acc[j], 2 * V4);
            if (eg == 0) acc[j] += t;
        }
#pragma unroll
        for (int j = 0; j < 8; j++) {
            float t = __shfl_down_sync(m, acc[j], V4);
            if (eg == 0) acc[j] += t;
        }
    }

    if (eg == 0) {
        float4* po = (float4*)(out + (size_t)node * CH);
        po[2 * c]     = make_float4(acc[0], acc[1], acc[2], acc[3]);
        po[2 * c + 1] = make_float4(acc[4], acc[5], acc[6], acc[7]);
    }
}

// ---------------- launch ----------------------------------------------------
extern "C" void kernel_launch(void* const* d_in, const int* in_sizes, int n_in,
                              void* d_out, int out_size) {
    const float* x  = (const float*)d_in[0];
    const int*   ei = (const int*)d_in[1];
    const float* W1 = (const float*)d_in[2];
    const float* b1 = (const float*)d_in[3];
    const float* W2 = (const float*)d_in[4];
    const float* b2 = (const float*)d_in[5];
    float*       out = (float*)d_out;

    void *hw_p, *agg1_p, *h2w_p;
    cudaGetSymbolAddress(&hw_p,   g_hw);
    cudaGetSymbolAddress(&agg1_p, g_agg1);
    cudaGetSymbolAddress(&h2w_p,  g_h2w);

    constexpr int TPB = 256;

    detect_kernel<<<1, 128>>>(ei);
    deg_kernel<<<NB_EDGE4, 256>>>(ei);
    scanA_kernel<<<SCAN_NB, SCAN_TPB>>>();
    // gemm1 stays launch #4 (ncu window lands here)
    gemm1_kernel<<<(N_NODES + 127) / 128, 256>>>(x, W1, (__half*)hw_p, N_NODES);
    scanC_kernel<<<SCAN_NB, SCAN_TPB>>>();
    fill_kernel<<<NB_EDGE4, 256>>>(ei);

    const int nb_warps = (N_NODES * 32 + TPB - 1) / TPB;
    aggregate_kernel<HIDDEN, false><<<nb_warps, TPB>>>((const __half*)hw_p, b1, (float*)agg1_p);

    constexpr int SMEM2 = (128 * (HIDDEN + 4) + HIDDEN * NCLS) * sizeof(float); // 45056
    cudaFuncSetAttribute(gemm2_kernel, cudaFuncAttributeMaxDynamicSharedMemorySize, SMEM2);
    gemm2_kernel<<<(N_NODES + 127) / 128, 160, SMEM2>>>((const float*)agg1_p, W2,
                                                        (__half*)h2w_p, N_NODES);

    aggregate_kernel<NCLS, true><<<nb_warps, TPB>>>((const __half*)h2w_p, b2, out);
}

// round 12
// speedup vs baseline: 1.8004x; 1.1854x over previous
#include <cuda_runtime.h>
#include <cuda_fp16.h>
#include <cstdint>

#define N_NODES 100000
#define N_EDGES 1600000
#define IN_CH   128
#define HIDDEN  64
#define NCLS    40

// ---------------- scratch (device globals; no allocation allowed) ----------
__device__ int   g_is64;
__device__ int   g_deg[N_NODES];       // zero at load; re-zeroed by agg2 tail
__device__ int   g_off[N_NODES + 1];
__device__ int   g_cur[N_NODES];
__device__ float g_dinv[N_NODES];
__device__ int   g_bsum[128];
__device__ unsigned g_adj[N_EDGES];    // (src<<15) | fp16(norm) sans sign, dst-grouped
__device__ __align__(16) __half g_hw  [(size_t)N_NODES * HIDDEN];  // X @ W1 (fp16)
__device__ __align__(16) __half g_agg1[(size_t)N_NODES * HIDDEN];  // layer1 agg (fp16)
__device__ __align__(16) __half g_h2w [(size_t)N_NODES * NCLS];    // relu(agg1)@W2 (fp16)

// ---------------- helpers ----------------------------------------------------
__device__ __forceinline__ void h8_to_f8(uint4 v, float* f) {
    float2 t;
    t = __half22float2(*(__half2*)&v.x); f[0] = t.x; f[1] = t.y;
    t = __half22float2(*(__half2*)&v.y); f[2] = t.x; f[3] = t.y;
    t = __half22float2(*(__half2*)&v.z); f[4] = t.x; f[5] = t.y;
    t = __half22float2(*(__half2*)&v.w); f[6] = t.x; f[7] = t.y;
}
__device__ __forceinline__ unsigned pack_h2(float a, float b) {
    __half2 h = __float22half2_rn(make_float2(a, b));
    return *(unsigned*)&h;
}
__device__ __forceinline__ unsigned relu_h2(unsigned v) {
    __half2 h = *(__half2*)&v;
    h = __hmax2(h, __half2half2(__ushort_as_half(0)));
    return *(unsigned*)&h;
}

#define NB_EDGE4 1563
#define EDGE4_T  (NB_EDGE4 * 256)

// ---------------- deg: in-block dtype detect + degree histogram -------------
// int64 indices (<2^31) have zero high words at every odd int32 position.
__global__ void deg_kernel(const int* __restrict__ w) {
    int v = w[2 * threadIdx.x + 1] | w[2 * ((int)threadIdx.x + 256) + 1];
    int is64 = !__syncthreads_or(v);
    if (blockIdx.x == 0 && threadIdx.x == 0) g_is64 = is64;   // for fill_kernel

    int idx = blockIdx.x * 256 + threadIdx.x;
#pragma unroll
    for (int j = 0; j < 4; j++) {
        int e = idx + j * EDGE4_T;
        if (e < N_EDGES) {
            int d = is64 ? w[2 * (N_EDGES + e)] : w[N_EDGES + e];
            if ((unsigned)d >= N_NODES) d = 0;
            atomicAdd(&g_deg[d], 1);
        }
    }
}

// ---------------- scan ------------------------------------------------------
#define SCAN_NB  128
#define SCAN_TPB 256
#define SCAN_PER 4

__global__ void scanA_kernel() {
    __shared__ int red[SCAN_TPB];
    int t = threadIdx.x;
    int base = (blockIdx.x * SCAN_TPB + t) * SCAN_PER;
    int s = 0;
#pragma unroll
    for (int j = 0; j < SCAN_PER; j++) {
        int i = base + j;
        if (i < N_NODES) s += g_deg[i];
    }
    red[t] = s;
    __syncthreads();
    for (int o = SCAN_TPB / 2; o > 0; o >>= 1) {
        if (t < o) red[t] += red[t + o];
        __syncthreads();
    }
    if (t == 0) g_bsum[blockIdx.x] = red[0];
}

__global__ void scanC_kernel() {
    __shared__ int top[SCAN_NB];
    __shared__ int p[SCAN_TPB];
    int t = threadIdx.x;

    if (t < SCAN_NB) top[t] = g_bsum[t];
    __syncthreads();
    for (int o = 1; o < SCAN_NB; o <<= 1) {
        int v = (t >= o && t < SCAN_NB) ? top[t - o] : 0;
        __syncthreads();
        if (t < SCAN_NB) top[t] += v;
        __syncthreads();
    }
    int bpre = (blockIdx.x > 0) ? top[blockIdx.x - 1] : 0;
    if (blockIdx.x == SCAN_NB - 1 && t == 0) g_off[N_NODES] = top[SCAN_NB - 1];

    int base = (blockIdx.x * SCAN_TPB + t) * SCAN_PER;
    int loc[SCAN_PER];
    int s = 0;
#pragma unroll
    for (int j = 0; j < SCAN_PER; j++) {
        int i = base + j;
        int d = (i < N_NODES) ? g_deg[i] : 0;
        loc[j] = s;
        s += d;
    }
    p[t] = s;
    __syncthreads();
    for (int o = 1; o < SCAN_TPB; o <<= 1) {
        int v = (t >= o) ? p[t - o] : 0;
        __syncthreads();
        p[t] += v;
        __syncthreads();
    }
    int pre = bpre + ((t > 0) ? p[t - 1] : 0);
#pragma unroll
    for (int j = 0; j < SCAN_PER; j++) {
        int i = base + j;
        if (i < N_NODES) {
            int o = pre + loc[j];
            g_off[i] = o;
            g_cur[i] = o;
            g_dinv[i] = rsqrtf((float)(g_deg[i] + 1));  // +1 self loop
        }
    }
}

// counting-sort edges by dst; packed entry = (src<<15) | fp16(norm) [sign=0]
__global__ void fill_kernel(const int* __restrict__ w) {
    int idx = blockIdx.x * 256 + threadIdx.x;
    int is64 = g_is64;
#pragma unroll
    for (int j = 0; j < 4; j++) {
        int e = idx + j * EDGE4_T;
        if (e < N_EDGES) {
            int s, d;
            if (is64) { s = w[2 * e]; d = w[2 * (N_EDGES + e)]; }
            else      { s = w[e];     d = w[N_EDGES + e]; }
            if ((unsigned)s >= N_NODES) s = 0;
            if ((unsigned)d >= N_NODES) d = 0;
            int pos = atomicAdd(&g_cur[d], 1);
            __half h = __float2half_rn(g_dinv[s] * g_dinv[d]);   // in (0,1]: sign bit 0
            g_adj[pos] = ((unsigned)s << 15) | (unsigned)__half_as_ushort(h);
        }
    }
}

// ---------------- GEMM1 (tensor core, A direct from gmem) -------------------
// fp16 C[M,64] = A[M,128](fp32) * W[128,64]; 256 thr = 8 warps x 16 rows.
#define SW_PITCH 72    // halfs per W smem row (64 + 8 pad)

__global__ __launch_bounds__(256) void gemm1_kernel(const float* __restrict__ A,
                                                    const float* __restrict__ W,
                                                    __half* __restrict__ C, int M) {
    __shared__ __half sW[128 * SW_PITCH];  // 18432 B
    const int tid = threadIdx.x;

    for (int i = tid; i < 128 * 16; i += 256) {
        int r  = i >> 4;
        int c4 = (i & 15) * 4;
        float4 a = *(const float4*)(W + r * HIDDEN + c4);
        *(uint2*)(sW + r * SW_PITCH + c4) = make_uint2(pack_h2(a.x, a.y), pack_h2(a.z, a.w));
    }
    __syncthreads();

    const int warp = tid >> 5, lane = tid & 31;
    const int r0 = blockIdx.x * 128 + warp * 16 + (lane >> 2);
    const int r1 = r0 + 8;
    const float* pA0 = A + (size_t)(r0 < M ? r0 : 0) * IN_CH + (lane & 3) * 2;
    const float* pA1 = A + (size_t)(r1 < M ? r1 : 0) * IN_CH + (lane & 3) * 2;

    const int lr  = lane & 7;
    const int seg = lane >> 3;
    const int b_kr   = (seg & 1) * 8 + lr;
    const int b_toff = (seg >> 1);

    float acc[8][4];
#pragma unroll
    for (int t = 0; t < 8; t++)
#pragma unroll
        for (int j = 0; j < 4; j++) acc[t][j] = 0.f;

#pragma unroll
    for (int s = 0; s < 8; s++) {
        float2 f;
        unsigned a0, a1, a2, a3;
        f = *(const float2*)(pA0 + s * 16);     a0 = pack_h2(f.x, f.y);
        f = *(const float2*)(pA1 + s * 16);     a1 = pack_h2(f.x, f.y);
        f = *(const float2*)(pA0 + s * 16 + 8); a2 = pack_h2(f.x, f.y);
        f = *(const float2*)(pA1 + s * 16 + 8); a3 = pack_h2(f.x, f.y);

        unsigned b[8][2];
#pragma unroll
        for (int tp = 0; tp < 4; tp++) {
            unsigned bd = (unsigned)__cvta_generic_to_shared(
                sW + (s * 16 + b_kr) * SW_PITCH + (2 * tp + b_toff) * 8);
            unsigned q0, q1, q2, q3;
            asm volatile("ldmatrix.sync.aligned.m8n8.x4.trans.shared.b16 {%0,%1,%2,%3}, [%4];"
                         : "=r"(q0), "=r"(q1), "=r"(q2), "=r"(q3) : "r"(bd));
            b[2 * tp][0] = q0; b[2 * tp][1] = q1;
            b[2 * tp + 1][0] = q2; b[2 * tp + 1][1] = q3;
        }
#pragma unroll
        for (int t = 0; t < 8; t++) {
            asm volatile(
                "mma.sync.aligned.m16n8k16.row.col.f32.f16.f16.f32 "
                "{%0,%1,%2,%3}, {%4,%5,%6,%7}, {%8,%9}, {%0,%1,%2,%3};"
                : "+f"(acc[t][0]), "+f"(acc[t][1]), "+f"(acc[t][2]), "+f"(acc[t][3])
                : "r"(a0), "r"(a1), "r"(a2), "r"(a3), "r"(b[t][0]), "r"(b[t][1]));
        }
    }

    const int cb = (lane & 3) * 2;
#pragma unroll
    for (int t = 0; t < 8; t++) {
        int col = t * 8 + cb;
        if (r0 < M)
            *(unsigned*)(C + (size_t)r0 * HIDDEN + col) = pack_h2(acc[t][0], acc[t][1]);
        if (r1 < M)
            *(unsigned*)(C + (size_t)r1 * HIDDEN + col) = pack_h2(acc[t][2], acc[t][3]);
    }
}

// ---------------- GEMM2 (tensor core): fp16 C[M,40]=relu(A[M,64]fp16)*W[64,40]
#define SW2_PITCH 40   // halfs; 80 B rows: 16B-aligned, bank stride 20 (conflict-free)

__global__ __launch_bounds__(256) void gemm2_kernel(const __half* __restrict__ A,
                                                    const float* __restrict__ W,
                                                    __half* __restrict__ C, int M) {
    __shared__ __half sW[64 * SW2_PITCH];  // 5120 B
    const int tid = threadIdx.x;

    for (int i = tid; i < 64 * 10; i += 256) {   // 64 rows x 10 float4
        int r = i / 10, c4 = (i - r * 10) * 4;
        float4 a = *(const float4*)(W + r * NCLS + c4);
        *(uint2*)(sW + r * SW2_PITCH + c4) = make_uint2(pack_h2(a.x, a.y), pack_h2(a.z, a.w));
    }
    __syncthreads();

    const int warp = tid >> 5, lane = tid & 31;
    const int r0 = blockIdx.x * 128 + warp * 16 + (lane >> 2);
    const int r1 = r0 + 8;
    const __half* pA0 = A + (size_t)(r0 < M ? r0 : 0) * HIDDEN + (lane & 3) * 2;
    const __half* pA1 = A + (size_t)(r1 < M ? r1 : 0) * HIDDEN + (lane & 3) * 2;

    const int lr  = lane & 7;
    const int seg = lane >> 3;
    const int b_kr   = (seg & 1) * 8 + lr;
    const int b_toff = (seg >> 1);
    const int l15 = lane & 15;

    float acc[5][4];
#pragma unroll
    for (int t = 0; t < 5; t++)
#pragma unroll
        for (int j = 0; j < 4; j++) acc[t][j] = 0.f;

#pragma unroll
    for (int s = 0; s < 4; s++) {          // k-steps of 16 (K=64)
        unsigned a0 = relu_h2(*(const unsigned*)(pA0 + s * 16));
        unsigned a1 = relu_h2(*(const unsigned*)(pA1 + s * 16));
        unsigned a2 = relu_h2(*(const unsigned*)(pA0 + s * 16 + 8));
        unsigned a3 = relu_h2(*(const unsigned*)(pA1 + s * 16 + 8));

        unsigned b[5][2];
#pragma unroll
        for (int tp = 0; tp < 2; tp++) {   // tiles 0-3 via two x4
            unsigned bd = (unsigned)__cvta_generic_to_shared(
                sW + (s * 16 + b_kr) * SW2_PITCH + (2 * tp + b_toff) * 8);
            unsigned q0, q1, q2, q3;
            asm volatile("ldmatrix.sync.aligned.m8n8.x4.trans.shared.b16 {%0,%1,%2,%3}, [%4];"
                         : "=r"(q0), "=r"(q1), "=r"(q2), "=r"(q3) : "r"(bd));
            b[2 * tp][0] = q0; b[2 * tp][1] = q1;
            b[2 * tp + 1][0] = q2; b[2 * tp + 1][1] = q3;
        }
        {   // tile 4 via x2 (lanes 0-15 supply addresses)
            unsigned bd = (unsigned)__cvta_generic_to_shared(
                sW + (s * 16 + (l15 >> 3) * 8 + (l15 & 7)) * SW2_PITCH + 32);
            unsigned q0, q1;
            asm volatile("ldmatrix.sync.aligned.m8n8.x2.trans.shared.b16 {%0,%1}, [%2];"
                         : "=r"(q0), "=r"(q1) : "r"(bd));
            b[4][0] = q0; b[4][1] = q1;
        }
#pragma unroll
        for (int t = 0; t < 5; t++) {
            asm volatile(
                "mma.sync.aligned.m16n8k16.row.col.f32.f16.f16.f32 "
                "{%0,%1,%2,%3}, {%4,%5,%6,%7}, {%8,%9}, {%0,%1,%2,%3};"
                : "+f"(acc[t][0]), "+f"(acc[t][1]), "+f"(acc[t][2]), "+f"(acc[t][3])
                : "r"(a0), "r"(a1), "r"(a2), "r"(a3), "r"(b[t][0]), "r"(b[t][1]));
        }
    }

    const int cb = (lane & 3) * 2;
#pragma unroll
    for (int t = 0; t < 5; t++) {
        int col = t * 8 + cb;
        if (r0 < M)
            *(unsigned*)(C + (size_t)r0 * NCLS + col) = pack_h2(acc[t][0], acc[t][1]);
        if (r1 < M)
            *(unsigned*)(C + (size_t)r1 * NCLS + col) = pack_h2(acc[t][2], acc[t][3]);
    }
}

// ---------------- CSR aggregation (fp16 gathers, fp32 accumulate) -----------
// adj entry: (src<<15)|fp16(norm); dummy 0 -> src 0, norm 0 (safe).
// OutT = __half (layer1, feeds gemm2) or float (layer2, final output).
template<int CH, bool ZERO_DEG, typename OutT>
__global__ void aggregate_kernel(const __half* __restrict__ feat,
                                 const float* __restrict__ bias,
                                 OutT* __restrict__ out) {
    constexpr int V4 = CH / 8;       // 8 (CH=64) or 5 (CH=40)
    constexpr int EP = 32 / V4;      // 4 or 6
    int node = (blockIdx.x * blockDim.x + threadIdx.x) >> 5;
    if (node >= N_NODES) return;
    int lane = threadIdx.x & 31;
    int eg = lane / V4;
    int c  = lane - eg * V4;
    bool act = eg < EP;

    if (ZERO_DEG && lane == 0) g_deg[node] = 0;

    const int beg = g_off[node];
    const int end = g_off[node + 1];

    float acc[8];
#pragma unroll
    for (int j = 0; j < 8; j++) acc[j] = 0.f;

    if (eg == 0) {                   // self-loop + bias in group 0 only
        float dv = g_dinv[node];
        float s  = dv * dv;
        uint4 f = ((const uint4*)(feat + (size_t)node * CH))[c];
        float ff[8]; h8_to_f8(f, ff);
        float4 b0 = ((const float4*)bias)[2 * c];
        float4 b1 = ((const float4*)bias)[2 * c + 1];
        acc[0] = fmaf(s, ff[0], b0.x); acc[1] = fmaf(s, ff[1], b0.y);
        acc[2] = fmaf(s, ff[2], b0.z); acc[3] = fmaf(s, ff[3], b0.w);
        acc[4] = fmaf(s, ff[4], b1.x); acc[5] = fmaf(s, ff[5], b1.y);
        acc[6] = fmaf(s, ff[6], b1.z); acc[7] = fmaf(s, ff[7], b1.w);
    }

    unsigned p = 0u;
    if (act && beg + eg < end) p = g_adj[beg + eg];
    for (int k = beg; k < end; k += EP) {
        int kn = k + EP;
        unsigned pn = 0u;
        if (act && kn + eg < end) pn = g_adj[kn + eg];
        int   src = (int)(p >> 15);
        float nrm = __half2float(__ushort_as_half((unsigned short)(p & 0x7FFFu)));
        uint4 v = ((const uint4*)(feat + (size_t)src * CH))[c];
        float ff[8]; h8_to_f8(v, ff);
#pragma unroll
        for (int j = 0; j < 8; j++) acc[j] = fmaf(nrm, ff[j], acc[j]);
        p = pn;
    }

    const unsigned m = 0xffffffffu;
    if (EP == 4) {
#pragma unroll
        for (int j = 0; j < 8; j++) acc[j] += __shfl_down_sync(m, acc[j], 2 * V4);
#pragma unroll
        for (int j = 0; j < 8; j++) acc[j] += __shfl_down_sync(m, acc[j], V4);
    } else {  // EP == 6
#pragma unroll
        for (int j = 0; j < 8; j++) acc[j] += __shfl_down_sync(m, acc[j], 3 * V4);
#pragma unroll
        for (int j = 0; j < 8; j++) {
            float t = __shfl_down_sync(m, acc[j], 2 * V4);
            if (eg == 0) acc[j] += t;
        }
#pragma unroll
        for (int j = 0; j < 8; j++) {
            float t = __shfl_down_sync(m, acc[j], V4);
            if (eg == 0) acc[j] += t;
        }
    }

    if (eg == 0) {
        if (sizeof(OutT) == 2) {     // fp16 output: 8 halves = one uint4
            uint4 u;
            u.x = pack_h2(acc[0], acc[1]);
            u.y = pack_h2(acc[2], acc[3]);
            u.z = pack_h2(acc[4], acc[5]);
            u.w = pack_h2(acc[6], acc[7]);
            ((uint4*)((__half*)out + (size_t)node * CH))[c] = u;
        } else {                     // fp32 output
            float4* po = (float4*)((float*)out + (size_t)node * CH);
            po[2 * c]     = make_float4(acc[0], acc[1], acc[2], acc[3]);
            po[2 * c + 1] = make_float4(acc[4], acc[5], acc[6], acc[7]);
        }
    }
}

// ---------------- launch ----------------------------------------------------
extern "C" void kernel_launch(void* const* d_in, const int* in_sizes, int n_in,
                              void* d_out, int out_size) {
    const float* x  = (const float*)d_in[0];
    const int*   ei = (const int*)d_in[1];
    const float* W1 = (const float*)d_in[2];
    const float* b1 = (const float*)d_in[3];
    const float* W2 = (const float*)d_in[4];
    const float* b2 = (const float*)d_in[5];
    float*       out = (float*)d_out;

    void *hw_p, *agg1_p, *h2w_p;
    cudaGetSymbolAddress(&hw_p,   g_hw);
    cudaGetSymbolAddress(&agg1_p, g_agg1);
    cudaGetSymbolAddress(&h2w_p,  g_h2w);

    constexpr int TPB = 256;

    // 1) degree histogram (dtype detect folded in)
    deg_kernel<<<NB_EDGE4, 256>>>(ei);
    // 2) per-block degree sums
    scanA_kernel<<<SCAN_NB, SCAN_TPB>>>();
    // 3) gemm1 (independent)
    gemm1_kernel<<<(N_NODES + 127) / 128, 256>>>(x, W1, (__half*)hw_p, N_NODES);
    // 4) full scan -> off/cur/dinv
    scanC_kernel<<<SCAN_NB, SCAN_TPB>>>();
    // 5) counting sort into dst-grouped packed adjacency
    fill_kernel<<<NB_EDGE4, 256>>>(ei);

    // 6) layer1 aggregation (+bias,+self) -> fp16
    const int nb_warps = (N_NODES * 32 + TPB - 1) / TPB;
    aggregate_kernel<HIDDEN, false, __half>
        <<<nb_warps, TPB>>>((const __half*)hw_p, b1, (__half*)agg1_p);

    // 7) gemm2 (tensor core, relu fused into A fragment loads)
    gemm2_kernel<<<(N_NODES + 127) / 128, 256>>>((const __half*)agg1_p, W2,
                                                 (__half*)h2w_p, N_NODES);

    // 8) layer2 aggregation -> fp32 output (re-zeroes g_deg for next call)
    aggregate_kernel<NCLS, true, float>
        <<<nb_warps, TPB>>>((const __half*)h2w_p, b2, out);
}

// round 13
// speedup vs baseline: 1.8216x; 1.0118x over previous
#include <cuda_runtime.h>
#include <cuda_fp16.h>
#include <cstdint>

#define N_NODES 100000
#define N_EDGES 1600000
#define IN_CH   128
#define HIDDEN  64
#define NCLS    40

// ---------------- scratch (device globals; no allocation allowed) ----------
__device__ int   g_is64;
__device__ int   g_deg[N_NODES];       // zero at load; re-zeroed by agg2 tail
__device__ int   g_off[N_NODES + 1];
__device__ int   g_cur[N_NODES];
__device__ float g_dinv[N_NODES];
__device__ int   g_bsum[128];          // lookback partials (sentinel +1); reset by deg
__device__ unsigned g_adj[N_EDGES];    // (src<<15) | fp16(norm) sans sign, dst-grouped
__device__ __align__(16) __half g_hw  [(size_t)N_NODES * HIDDEN];  // X @ W1 (fp16)
__device__ __align__(16) __half g_agg1[(size_t)N_NODES * HIDDEN];  // layer1 agg (fp16)
__device__ __align__(16) __half g_h2w [(size_t)N_NODES * NCLS];    // relu(agg1)@W2 (fp16)

// ---------------- helpers ----------------------------------------------------
__device__ __forceinline__ void h8_to_f8(uint4 v, float* f) {
    float2 t;
    t = __half22float2(*(__half2*)&v.x); f[0] = t.x; f[1] = t.y;
    t = __half22float2(*(__half2*)&v.y); f[2] = t.x; f[3] = t.y;
    t = __half22float2(*(__half2*)&v.z); f[4] = t.x; f[5] = t.y;
    t = __half22float2(*(__half2*)&v.w); f[6] = t.x; f[7] = t.y;
}
__device__ __forceinline__ unsigned pack_h2(float a, float b) {
    __half2 h = __float22half2_rn(make_float2(a, b));
    return *(unsigned*)&h;
}
__device__ __forceinline__ unsigned relu_h2(unsigned v) {
    __half2 h = *(__half2*)&v;
    h = __hmax2(h, __half2half2(__ushort_as_half(0)));
    return *(unsigned*)&h;
}

#define NB_EDGE4 1563
#define EDGE4_T  (NB_EDGE4 * 256)
#define SCAN_NB  128
#define SCAN_TPB 256
#define SCAN_PER 4        // 128*256*4 = 131072 >= N_NODES

// ---------------- deg: dtype detect + g_bsum reset + degree histogram -------
// int64 indices (<2^31) have zero high words at every odd int32 position.
__global__ void deg_kernel(const int* __restrict__ w) {
    int v = w[2 * threadIdx.x + 1] | w[2 * ((int)threadIdx.x + 256) + 1];
    int is64 = !__syncthreads_or(v);
    if (blockIdx.x == 0) {
        if (threadIdx.x == 0) g_is64 = is64;          // for fill_kernel
        if (threadIdx.x < SCAN_NB) g_bsum[threadIdx.x] = 0;  // reset lookback state
    }

    int idx = blockIdx.x * 256 + threadIdx.x;
#pragma unroll
    for (int j = 0; j < 4; j++) {
        int e = idx + j * EDGE4_T;
        if (e < N_EDGES) {
            int d = is64 ? w[2 * (N_EDGES + e)] : w[N_EDGES + e];
            if ((unsigned)d >= N_NODES) d = 0;
            atomicAdd(&g_deg[d], 1);
        }
    }
}

// ---------------- single-kernel exclusive scan (decoupled lookback) ---------
// 128 blocks (all co-resident on 148 SMs). Each block: local prefix, publish
// total+1, poll all predecessor partials (1-2 L2 lines), reduce, write outputs.
__global__ void scan_kernel() {
    __shared__ int p[SCAN_TPB];
    __shared__ int red[SCAN_TPB];
    const int t = threadIdx.x;
    const int bid = blockIdx.x;

    int base = (bid * SCAN_TPB + t) * SCAN_PER;
    int loc[SCAN_PER];
    int s = 0;
#pragma unroll
    for (int j = 0; j < SCAN_PER; j++) {
        int i = base + j;
        int d = (i < N_NODES) ? g_deg[i] : 0;
        loc[j] = s;
        s += d;
    }
    p[t] = s;
    __syncthreads();
    for (int o = 1; o < SCAN_TPB; o <<= 1) {
        int v = (t >= o) ? p[t - o] : 0;
        __syncthreads();
        p[t] += v;
        __syncthreads();
    }
    int total = p[SCAN_TPB - 1];

    if (t == 0) {
        __threadfence();                       // local prefix visible first (paranoia)
        atomicExch(&g_bsum[bid], total + 1);   // publish with sentinel
    }

    // lookback: thread t polls predecessor t (t < bid)
    int v = 0;
    if (t < bid) {
        while ((v = atomicAdd(&g_bsum[t], 0)) == 0) { }
        v -= 1;
    }
    red[t] = v;
    __syncthreads();
    for (int o = SCAN_TPB / 2; o > 0; o >>= 1) {
        if (t < o) red[t] += red[t + o];
        __syncthreads();
    }
    int bpre = red[0];
    if (bid == SCAN_NB - 1 && t == 0) g_off[N_NODES] = bpre + total;

    int pre = bpre + ((t > 0) ? p[t - 1] : 0);
#pragma unroll
    for (int j = 0; j < SCAN_PER; j++) {
        int i = base + j;
        if (i < N_NODES) {
            int o = pre + loc[j];
            g_off[i] = o;
            g_cur[i] = o;
            g_dinv[i] = rsqrtf((float)(g_deg[i] + 1));  // +1 self loop
        }
    }
}

// counting-sort edges by dst; packed entry = (src<<15) | fp16(norm) [sign=0]
__global__ void fill_kernel(const int* __restrict__ w) {
    int idx = blockIdx.x * 256 + threadIdx.x;
    int is64 = g_is64;
#pragma unroll
    for (int j = 0; j < 4; j++) {
        int e = idx + j * EDGE4_T;
        if (e < N_EDGES) {
            int s, d;
            if (is64) { s = w[2 * e]; d = w[2 * (N_EDGES + e)]; }
            else      { s = w[e];     d = w[N_EDGES + e]; }
            if ((unsigned)s >= N_NODES) s = 0;
            if ((unsigned)d >= N_NODES) d = 0;
            int pos = atomicAdd(&g_cur[d], 1);
            __half h = __float2half_rn(g_dinv[s] * g_dinv[d]);   // in (0,1]: sign bit 0
            g_adj[pos] = ((unsigned)s << 15) | (unsigned)__half_as_ushort(h);
        }
    }
}

// ---------------- GEMM1 (tensor core, A direct from gmem, pipelined) --------
// fp16 C[M,64] = A[M,128](fp32) * W[128,64]; 256 thr = 8 warps x 16 rows.
// A fragment loads software-pipelined 2 k-steps ahead of the MMAs.
#define SW_PITCH 72    // halfs per W smem row (64 + 8 pad)

__global__ __launch_bounds__(256) void gemm1_kernel(const float* __restrict__ A,
                                                    const float* __restrict__ W,
                                                    __half* __restrict__ C, int M) {
    __shared__ __half sW[128 * SW_PITCH];  // 18432 B
    const int tid = threadIdx.x;

    for (int i = tid; i < 128 * 16; i += 256) {
        int r  = i >> 4;
        int c4 = (i & 15) * 4;
        float4 a = *(const float4*)(W + r * HIDDEN + c4);
        *(uint2*)(sW + r * SW_PITCH + c4) = make_uint2(pack_h2(a.x, a.y), pack_h2(a.z, a.w));
    }
    __syncthreads();

    const int warp = tid >> 5, lane = tid & 31;
    const int r0 = blockIdx.x * 128 + warp * 16 + (lane >> 2);
    const int r1 = r0 + 8;
    const float* pA0 = A + (size_t)(r0 < M ? r0 : 0) * IN_CH + (lane & 3) * 2;
    const float* pA1 = A + (size_t)(r1 < M ? r1 : 0) * IN_CH + (lane & 3) * 2;

    const int lr  = lane & 7;
    const int seg = lane >> 3;
    const int b_kr   = (seg & 1) * 8 + lr;
    const int b_toff = (seg >> 1);

    float acc[8][4];
#pragma unroll
    for (int t = 0; t < 8; t++)
#pragma unroll
        for (int j = 0; j < 4; j++) acc[t][j] = 0.f;

    // depth-2 A staging
    float2 f[2][4];
#pragma unroll
    for (int q = 0; q < 2; q++) {
        f[q][0] = *(const float2*)(pA0 + q * 16);
        f[q][1] = *(const float2*)(pA1 + q * 16);
        f[q][2] = *(const float2*)(pA0 + q * 16 + 8);
        f[q][3] = *(const float2*)(pA1 + q * 16 + 8);
    }

#pragma unroll
    for (int s = 0; s < 8; s++) {
        unsigned a0 = pack_h2(f[s & 1][0].x, f[s & 1][0].y);
        unsigned a1 = pack_h2(f[s & 1][1].x, f[s & 1][1].y);
        unsigned a2 = pack_h2(f[s & 1][2].x, f[s & 1][2].y);
        unsigned a3 = pack_h2(f[s & 1][3].x, f[s & 1][3].y);
        if (s + 2 < 8) {   // prefetch step s+2 into the slot just consumed
            f[s & 1][0] = *(const float2*)(pA0 + (s + 2) * 16);
            f[s & 1][1] = *(const float2*)(pA1 + (s + 2) * 16);
            f[s & 1][2] = *(const float2*)(pA0 + (s + 2) * 16 + 8);
            f[s & 1][3] = *(const float2*)(pA1 + (s + 2) * 16 + 8);
        }

        unsigned b[8][2];
#pragma unroll
        for (int tp = 0; tp < 4; tp++) {
            unsigned bd = (unsigned)__cvta_generic_to_shared(
                sW + (s * 16 + b_kr) * SW_PITCH + (2 * tp + b_toff) * 8);
            unsigned q0, q1, q2, q3;
            asm volatile("ldmatrix.sync.aligned.m8n8.x4.trans.shared.b16 {%0,%1,%2,%3}, [%4];"
                         : "=r"(q0), "=r"(q1), "=r"(q2), "=r"(q3) : "r"(bd));
            b[2 * tp][0] = q0; b[2 * tp][1] = q1;
            b[2 * tp + 1][0] = q2; b[2 * tp + 1][1] = q3;
        }
#pragma unroll
        for (int t = 0; t < 8; t++) {
            asm volatile(
                "mma.sync.aligned.m16n8k16.row.col.f32.f16.f16.f32 "
                "{%0,%1,%2,%3}, {%4,%5,%6,%7}, {%8,%9}, {%0,%1,%2,%3};"
                : "+f"(acc[t][0]), "+f"(acc[t][1]), "+f"(acc[t][2]), "+f"(acc[t][3])
                : "r"(a0), "r"(a1), "r"(a2), "r"(a3), "r"(b[t][0]), "r"(b[t][1]));
        }
    }

    const int cb = (lane & 3) * 2;
#pragma unroll
    for (int t = 0; t < 8; t++) {
        int col = t * 8 + cb;
        if (r0 < M)
            *(unsigned*)(C + (size_t)r0 * HIDDEN + col) = pack_h2(acc[t][0], acc[t][1]);
        if (r1 < M)
            *(unsigned*)(C + (size_t)r1 * HIDDEN + col) = pack_h2(acc[t][2], acc[t][3]);
    }
}

// ---------------- GEMM2 (tensor core): fp16 C[M,40]=relu(A[M,64]fp16)*W[64,40]
#define SW2_PITCH 40   // halfs; 80 B rows: 16B-aligned, bank stride 20 (conflict-free)

__global__ __launch_bounds__(256) void gemm2_kernel(const __half* __restrict__ A,
                                                    const float* __restrict__ W,
                                                    __half* __restrict__ C, int M) {
    __shared__ __half sW[64 * SW2_PITCH];  // 5120 B
    const int tid = threadIdx.x;

    for (int i = tid; i < 64 * 10; i += 256) {   // 64 rows x 10 float4
        int r = i / 10, c4 = (i - r * 10) * 4;
        float4 a = *(const float4*)(W + r * NCLS + c4);
        *(uint2*)(sW + r * SW2_PITCH + c4) = make_uint2(pack_h2(a.x, a.y), pack_h2(a.z, a.w));
    }
    __syncthreads();

    const int warp = tid >> 5, lane = tid & 31;
    const int r0 = blockIdx.x * 128 + warp * 16 + (lane >> 2);
    const int r1 = r0 + 8;
    const __half* pA0 = A + (size_t)(r0 < M ? r0 : 0) * HIDDEN + (lane & 3) * 2;
    const __half* pA1 = A + (size_t)(r1 < M ? r1 : 0) * HIDDEN + (lane & 3) * 2;

    const int lr  = lane & 7;
    const int seg = lane >> 3;
    const int b_kr   = (seg & 1) * 8 + lr;
    const int b_toff = (seg >> 1);
    const int l15 = lane & 15;

    float acc[5][4];
#pragma unroll
    for (int t = 0; t < 5; t++)
#pragma unroll
        for (int j = 0; j < 4; j++) acc[t][j] = 0.f;

#pragma unroll
    for (int s = 0; s < 4; s++) {          // k-steps of 16 (K=64)
        unsigned a0 = relu_h2(*(const unsigned*)(pA0 + s * 16));
        unsigned a1 = relu_h2(*(const unsigned*)(pA1 + s * 16));
        unsigned a2 = relu_h2(*(const unsigned*)(pA0 + s * 16 + 8));
        unsigned a3 = relu_h2(*(const unsigned*)(pA1 + s * 16 + 8));

        unsigned b[5][2];
#pragma unroll
        for (int tp = 0; tp < 2; tp++) {   // tiles 0-3 via two x4
            unsigned bd = (unsigned)__cvta_generic_to_shared(
                sW + (s * 16 + b_kr) * SW2_PITCH + (2 * tp + b_toff) * 8);
            unsigned q0, q1, q2, q3;
            asm volatile("ldmatrix.sync.aligned.m8n8.x4.trans.shared.b16 {%0,%1,%2,%3}, [%4];"
                         : "=r"(q0), "=r"(q1), "=r"(q2), "=r"(q3) : "r"(bd));
            b[2 * tp][0] = q0; b[2 * tp][1] = q1;
            b[2 * tp + 1][0] = q2; b[2 * tp + 1][1] = q3;
        }
        {   // tile 4 via x2 (lanes 0-15 supply addresses)
            unsigned bd = (unsigned)__cvta_generic_to_shared(
                sW + (s * 16 + (l15 >> 3) * 8 + (l15 & 7)) * SW2_PITCH + 32);
            unsigned q0, q1;
            asm volatile("ldmatrix.sync.aligned.m8n8.x2.trans.shared.b16 {%0,%1}, [%2];"
                         : "=r"(q0), "=r"(q1) : "r"(bd));
            b[4][0] = q0; b[4][1] = q1;
        }
#pragma unroll
        for (int t = 0; t < 5; t++) {
            asm volatile(
                "mma.sync.aligned.m16n8k16.row.col.f32.f16.f16.f32 "
                "{%0,%1,%2,%3}, {%4,%5,%6,%7}, {%8,%9}, {%0,%1,%2,%3};"
                : "+f"(acc[t][0]), "+f"(acc[t][1]), "+f"(acc[t][2]), "+f"(acc[t][3])
                : "r"(a0), "r"(a1), "r"(a2), "r"(a3), "r"(b[t][0]), "r"(b[t][1]));
        }
    }

    const int cb = (lane & 3) * 2;
#pragma unroll
    for (int t = 0; t < 5; t++) {
        int col = t * 8 + cb;
        if (r0 < M)
            *(unsigned*)(C + (size_t)r0 * NCLS + col) = pack_h2(acc[t][0], acc[t][1]);
        if (r1 < M)
            *(unsigned*)(C + (size_t)r1 * NCLS + col) = pack_h2(acc[t][2], acc[t][3]);
    }
}

// ---------------- CSR aggregation (fp16 gathers, fp32 accumulate) -----------
// adj entry: (src<<15)|fp16(norm); dummy 0 -> src 0, norm 0 (safe).
template<int CH, bool ZERO_DEG, typename OutT>
__global__ void aggregate_kernel(const __half* __restrict__ feat,
                                 const float* __restrict__ bias,
                                 OutT* __restrict__ out) {
    constexpr int V4 = CH / 8;       // 8 (CH=64) or 5 (CH=40)
    constexpr int EP = 32 / V4;      // 4 or 6
    int node = (blockIdx.x * blockDim.x + threadIdx.x) >> 5;
    if (node >= N_NODES) return;
    int lane = threadIdx.x & 31;
    int eg = lane / V4;
    int c  = lane - eg * V4;
    bool act = eg < EP;

    if (ZERO_DEG && lane == 0) g_deg[node] = 0;

    const int beg = g_off[node];
    const int end = g_off[node + 1];

    float acc[8];
#pragma unroll
    for (int j = 0; j < 8; j++) acc[j] = 0.f;

    if (eg == 0) {                   // self-loop + bias in group 0 only
        float dv = g_dinv[node];
        float s  = dv * dv;
        uint4 f = ((const uint4*)(feat + (size_t)node * CH))[c];
        float ff[8]; h8_to_f8(f, ff);
        float4 b0 = ((const float4*)bias)[2 * c];
        float4 b1 = ((const float4*)bias)[2 * c + 1];
        acc[0] = fmaf(s, ff[0], b0.x); acc[1] = fmaf(s, ff[1], b0.y);
        acc[2] = fmaf(s, ff[2], b0.z); acc[3] = fmaf(s, ff[3], b0.w);
        acc[4] = fmaf(s, ff[4], b1.x); acc[5] = fmaf(s, ff[5], b1.y);
        acc[6] = fmaf(s, ff[6], b1.z); acc[7] = fmaf(s, ff[7], b1.w);
    }

    unsigned p = 0u;
    if (act && beg + eg < end) p = g_adj[beg + eg];
    for (int k = beg; k < end; k += EP) {
        int kn = k + EP;
        unsigned pn = 0u;
        if (act && kn + eg < end) pn = g_adj[kn + eg];
        int   src = (int)(p >> 15);
        float nrm = __half2float(__ushort_as_half((unsigned short)(p & 0x7FFFu)));
        uint4 v = ((const uint4*)(feat + (size_t)src * CH))[c];
        float ff[8]; h8_to_f8(v, ff);
#pragma unroll
        for (int j = 0; j < 8; j++) acc[j] = fmaf(nrm, ff[j], acc[j]);
        p = pn;
    }

    const unsigned m = 0xffffffffu;
    if (EP == 4) {
#pragma unroll
        for (int j = 0; j < 8; j++) acc[j] += __shfl_down_sync(m, acc[j], 2 * V4);
#pragma unroll
        for (int j = 0; j < 8; j++) acc[j] += __shfl_down_sync(m, acc[j], V4);
    } else {  // EP == 6
#pragma unroll
        for (int j = 0; j < 8; j++) acc[j] += __shfl_down_sync(m, acc[j], 3 * V4);
#pragma unroll
        for (int j = 0; j < 8; j++) {
            float t = __shfl_down_sync(m, acc[j], 2 * V4);
            if (eg == 0) acc[j] += t;
        }
#pragma unroll
        for (int j = 0; j < 8; j++) {
            float t = __shfl_down_sync(m, acc[j], V4);
            if (eg == 0) acc[j] += t;
        }
    }

    if (eg == 0) {
        if (sizeof(OutT) == 2) {     // fp16 output: 8 halves = one uint4
            uint4 u;
            u.x = pack_h2(acc[0], acc[1]);
            u.y = pack_h2(acc[2], acc[3]);
            u.z = pack_h2(acc[4], acc[5]);
            u.w = pack_h2(acc[6], acc[7]);
            ((uint4*)((__half*)out + (size_t)node * CH))[c] = u;
        } else {                     // fp32 output
            float4* po = (float4*)((float*)out + (size_t)node * CH);
            po[2 * c]     = make_float4(acc[0], acc[1], acc[2], acc[3]);
            po[2 * c + 1] = make_float4(acc[4], acc[5], acc[6], acc[7]);
        }
    }
}

// ---------------- launch ----------------------------------------------------
extern "C" void kernel_launch(void* const* d_in, const int* in_sizes, int n_in,
                              void* d_out, int out_size) {
    const float* x  = (const float*)d_in[0];
    const int*   ei = (const int*)d_in[1];
    const float* W1 = (const float*)d_in[2];
    const float* b1 = (const float*)d_in[3];
    const float* W2 = (const float*)d_in[4];
    const float* b2 = (const float*)d_in[5];
    float*       out = (float*)d_out;

    void *hw_p, *agg1_p, *h2w_p;
    cudaGetSymbolAddress(&hw_p,   g_hw);
    cudaGetSymbolAddress(&agg1_p, g_agg1);
    cudaGetSymbolAddress(&h2w_p,  g_h2w);

    constexpr int TPB = 256;

    // 1) degree histogram (dtype detect + lookback reset folded in)
    deg_kernel<<<NB_EDGE4, 256>>>(ei);
    // 2) gemm1 (independent)
    gemm1_kernel<<<(N_NODES + 127) / 128, 256>>>(x, W1, (__half*)hw_p, N_NODES);
    // 3) single-kernel scan -> off/cur/dinv
    scan_kernel<<<SCAN_NB, SCAN_TPB>>>();
    // 4) counting sort into dst-grouped packed adjacency
    fill_kernel<<<NB_EDGE4, 256>>>(ei);

    // 5) layer1 aggregation (+bias,+self) -> fp16
    const int nb_warps = (N_NODES * 32 + TPB - 1) / TPB;
    aggregate_kernel<HIDDEN, false, __half>
        <<<nb_warps, TPB>>>((const __half*)hw_p, b1, (__half*)agg1_p);

    // 6) gemm2 (tensor core, relu fused into A fragment loads)
    gemm2_kernel<<<(N_NODES + 127) / 128, 256>>>((const __half*)agg1_p, W2,
                                                 (__half*)h2w_p, N_NODES);

    // 7) layer2 aggregation -> fp32 output (re-zeroes g_deg for next call)
    aggregate_kernel<NCLS, true, float>
        <<<nb_warps, TPB>>>((const __half*)h2w_p, b2, out);
}

// round 14
// speedup vs baseline: 1.9095x; 1.0483x over previous
#include <cuda_runtime.h>
#include <cuda_fp16.h>
#include <cstdint>

#define N_NODES 100000
#define N_EDGES 1600000
#define IN_CH   128
#define HIDDEN  64
#define NCLS    40

// ---------------- scratch (device globals; no allocation allowed) ----------
__device__ int   g_is64;
__device__ int   g_deg[N_NODES];       // zero at load; re-zeroed by agg2 tail
__device__ int   g_off[N_NODES + 1];
__device__ int   g_cur[N_NODES];
__device__ float g_dinv[N_NODES];
__device__ int   g_bsum[128];          // lookback partials (sentinel +1); reset by deg
__device__ int   g_adj[N_EDGES];       // plain src index, dst-grouped
__device__ __align__(16) __half g_hw  [(size_t)N_NODES * HIDDEN];  // dinv*(X@W1) fp16
__device__ __align__(16) __half g_agg1[(size_t)N_NODES * HIDDEN];  // layer1 agg (fp16)
__device__ __align__(16) __half g_h2w [(size_t)N_NODES * NCLS];    // dinv*(relu@W2) fp16

// ---------------- helpers ----------------------------------------------------
__device__ __forceinline__ void h8_to_f8(uint4 v, float* f) {
    float2 t;
    t = __half22float2(*(__half2*)&v.x); f[0] = t.x; f[1] = t.y;
    t = __half22float2(*(__half2*)&v.y); f[2] = t.x; f[3] = t.y;
    t = __half22float2(*(__half2*)&v.z); f[4] = t.x; f[5] = t.y;
    t = __half22float2(*(__half2*)&v.w); f[6] = t.x; f[7] = t.y;
}
__device__ __forceinline__ unsigned pack_h2(float a, float b) {
    __half2 h = __float22half2_rn(make_float2(a, b));
    return *(unsigned*)&h;
}
__device__ __forceinline__ unsigned relu_h2(unsigned v) {
    __half2 h = *(__half2*)&v;
    h = __hmax2(h, __half2half2(__ushort_as_half(0)));
    return *(unsigned*)&h;
}

#define NB_EDGE4 1563
#define EDGE4_T  (NB_EDGE4 * 256)
#define SCAN_NB  128
#define SCAN_TPB 256
#define SCAN_PER 4        // 128*256*4 = 131072 >= N_NODES

// ---------------- deg: dtype detect + g_bsum reset + degree histogram -------
__global__ void deg_kernel(const int* __restrict__ w) {
    int v = w[2 * threadIdx.x + 1] | w[2 * ((int)threadIdx.x + 256) + 1];
    int is64 = !__syncthreads_or(v);
    if (blockIdx.x == 0) {
        if (threadIdx.x == 0) g_is64 = is64;
        if (threadIdx.x < SCAN_NB) g_bsum[threadIdx.x] = 0;
    }

    int idx = blockIdx.x * 256 + threadIdx.x;
#pragma unroll
    for (int j = 0; j < 4; j++) {
        int e = idx + j * EDGE4_T;
        if (e < N_EDGES) {
            int d = is64 ? w[2 * (N_EDGES + e)] : w[N_EDGES + e];
            if ((unsigned)d >= N_NODES) d = 0;
            atomicAdd(&g_deg[d], 1);
        }
    }
}

// ---------------- single-kernel exclusive scan (decoupled lookback) ---------
__global__ void scan_kernel() {
    __shared__ int p[SCAN_TPB];
    __shared__ int red[SCAN_TPB];
    const int t = threadIdx.x;
    const int bid = blockIdx.x;

    int base = (bid * SCAN_TPB + t) * SCAN_PER;
    int loc[SCAN_PER];
    int s = 0;
#pragma unroll
    for (int j = 0; j < SCAN_PER; j++) {
        int i = base + j;
        int d = (i < N_NODES) ? g_deg[i] : 0;
        loc[j] = s;
        s += d;
    }
    p[t] = s;
    __syncthreads();
    for (int o = 1; o < SCAN_TPB; o <<= 1) {
        int v = (t >= o) ? p[t - o] : 0;
        __syncthreads();
        p[t] += v;
        __syncthreads();
    }
    int total = p[SCAN_TPB - 1];

    if (t == 0) {
        __threadfence();
        atomicExch(&g_bsum[bid], total + 1);   // publish with sentinel
    }

    int v = 0;
    if (t < bid) {
        while ((v = atomicAdd(&g_bsum[t], 0)) == 0) { }
        v -= 1;
    }
    red[t] = v;
    __syncthreads();
    for (int o = SCAN_TPB / 2; o > 0; o >>= 1) {
        if (t < o) red[t] += red[t + o];
        __syncthreads();
    }
    int bpre = red[0];
    if (bid == SCAN_NB - 1 && t == 0) g_off[N_NODES] = bpre + total;

    int pre = bpre + ((t > 0) ? p[t - 1] : 0);
#pragma unroll
    for (int j = 0; j < SCAN_PER; j++) {
        int i = base + j;
        if (i < N_NODES) {
            int o = pre + loc[j];
            g_off[i] = o;
            g_cur[i] = o;
            g_dinv[i] = rsqrtf((float)(g_deg[i] + 1));  // +1 self loop
        }
    }
}

// counting-sort edges by dst; entry = plain src (weights folded into features)
__global__ void fill_kernel(const int* __restrict__ w) {
    int idx = blockIdx.x * 256 + threadIdx.x;
    int is64 = g_is64;
#pragma unroll
    for (int j = 0; j < 4; j++) {
        int e = idx + j * EDGE4_T;
        if (e < N_EDGES) {
            int s, d;
            if (is64) { s = w[2 * e]; d = w[2 * (N_EDGES + e)]; }
            else      { s = w[e];     d = w[N_EDGES + e]; }
            if ((unsigned)s >= N_NODES) s = 0;
            if ((unsigned)d >= N_NODES) d = 0;
            int pos = atomicAdd(&g_cur[d], 1);
            g_adj[pos] = s;
        }
    }
}

// ---------------- GEMM1 (tensor core, A direct from gmem, pipelined) --------
// fp16 C[M,64] = dinv[m] * (A[M,128](fp32) @ W[128,64]); 8 warps x 16 rows.
#define SW_PITCH 72

__global__ __launch_bounds__(256) void gemm1_kernel(const float* __restrict__ A,
                                                    const float* __restrict__ W,
                                                    __half* __restrict__ C, int M) {
    __shared__ __half sW[128 * SW_PITCH];
    const int tid = threadIdx.x;

    for (int i = tid; i < 128 * 16; i += 256) {
        int r  = i >> 4;
        int c4 = (i & 15) * 4;
        float4 a = *(const float4*)(W + r * HIDDEN + c4);
        *(uint2*)(sW + r * SW_PITCH + c4) = make_uint2(pack_h2(a.x, a.y), pack_h2(a.z, a.w));
    }
    __syncthreads();

    const int warp = tid >> 5, lane = tid & 31;
    const int r0 = blockIdx.x * 128 + warp * 16 + (lane >> 2);
    const int r1 = r0 + 8;
    const float* pA0 = A + (size_t)(r0 < M ? r0 : 0) * IN_CH + (lane & 3) * 2;
    const float* pA1 = A + (size_t)(r1 < M ? r1 : 0) * IN_CH + (lane & 3) * 2;

    const int lr  = lane & 7;
    const int seg = lane >> 3;
    const int b_kr   = (seg & 1) * 8 + lr;
    const int b_toff = (seg >> 1);

    float acc[8][4];
#pragma unroll
    for (int t = 0; t < 8; t++)
#pragma unroll
        for (int j = 0; j < 4; j++) acc[t][j] = 0.f;

    float2 f[2][4];
#pragma unroll
    for (int q = 0; q < 2; q++) {
        f[q][0] = *(const float2*)(pA0 + q * 16);
        f[q][1] = *(const float2*)(pA1 + q * 16);
        f[q][2] = *(const float2*)(pA0 + q * 16 + 8);
        f[q][3] = *(const float2*)(pA1 + q * 16 + 8);
    }

#pragma unroll
    for (int s = 0; s < 8; s++) {
        unsigned a0 = pack_h2(f[s & 1][0].x, f[s & 1][0].y);
        unsigned a1 = pack_h2(f[s & 1][1].x, f[s & 1][1].y);
        unsigned a2 = pack_h2(f[s & 1][2].x, f[s & 1][2].y);
        unsigned a3 = pack_h2(f[s & 1][3].x, f[s & 1][3].y);
        if (s + 2 < 8) {
            f[s & 1][0] = *(const float2*)(pA0 + (s + 2) * 16);
            f[s & 1][1] = *(const float2*)(pA1 + (s + 2) * 16);
            f[s & 1][2] = *(const float2*)(pA0 + (s + 2) * 16 + 8);
            f[s & 1][3] = *(const float2*)(pA1 + (s + 2) * 16 + 8);
        }

        unsigned b[8][2];
#pragma unroll
        for (int tp = 0; tp < 4; tp++) {
            unsigned bd = (unsigned)__cvta_generic_to_shared(
                sW + (s * 16 + b_kr) * SW_PITCH + (2 * tp + b_toff) * 8);
            unsigned q0, q1, q2, q3;
            asm volatile("ldmatrix.sync.aligned.m8n8.x4.trans.shared.b16 {%0,%1,%2,%3}, [%4];"
                         : "=r"(q0), "=r"(q1), "=r"(q2), "=r"(q3) : "r"(bd));
            b[2 * tp][0] = q0; b[2 * tp][1] = q1;
            b[2 * tp + 1][0] = q2; b[2 * tp + 1][1] = q3;
        }
#pragma unroll
        for (int t = 0; t < 8; t++) {
            asm volatile(
                "mma.sync.aligned.m16n8k16.row.col.f32.f16.f16.f32 "
                "{%0,%1,%2,%3}, {%4,%5,%6,%7}, {%8,%9}, {%0,%1,%2,%3};"
                : "+f"(acc[t][0]), "+f"(acc[t][1]), "+f"(acc[t][2]), "+f"(acc[t][3])
                : "r"(a0), "r"(a1), "r"(a2), "r"(a3), "r"(b[t][0]), "r"(b[t][1]));
        }
    }

    // epilogue: scale row by dinv[row], pack fp16
    const float dv0 = (r0 < M) ? g_dinv[r0] : 0.f;
    const float dv1 = (r1 < M) ? g_dinv[r1] : 0.f;
    const int cb = (lane & 3) * 2;
#pragma unroll
    for (int t = 0; t < 8; t++) {
        int col = t * 8 + cb;
        if (r0 < M)
            *(unsigned*)(C + (size_t)r0 * HIDDEN + col) = pack_h2(dv0 * acc[t][0], dv0 * acc[t][1]);
        if (r1 < M)
            *(unsigned*)(C + (size_t)r1 * HIDDEN + col) = pack_h2(dv1 * acc[t][2], dv1 * acc[t][3]);
    }
}

// ---------------- GEMM2 (tensor core): fp16 C[M,40]=dinv*(relu(A)@W[64,40]) -
#define SW2_PITCH 40

__global__ __launch_bounds__(256) void gemm2_kernel(const __half* __restrict__ A,
                                                    const float* __restrict__ W,
                                                    __half* __restrict__ C, int M) {
    __shared__ __half sW[64 * SW2_PITCH];
    const int tid = threadIdx.x;

    for (int i = tid; i < 64 * 10; i += 256) {
        int r = i / 10, c4 = (i - r * 10) * 4;
        float4 a = *(const float4*)(W + r * NCLS + c4);
        *(uint2*)(sW + r * SW2_PITCH + c4) = make_uint2(pack_h2(a.x, a.y), pack_h2(a.z, a.w));
    }
    __syncthreads();

    const int warp = tid >> 5, lane = tid & 31;
    const int r0 = blockIdx.x * 128 + warp * 16 + (lane >> 2);
    const int r1 = r0 + 8;
    const __half* pA0 = A + (size_t)(r0 < M ? r0 : 0) * HIDDEN + (lane & 3) * 2;
    const __half* pA1 = A + (size_t)(r1 < M ? r1 : 0) * HIDDEN + (lane & 3) * 2;

    const int lr  = lane & 7;
    const int seg = lane >> 3;
    const int b_kr   = (seg & 1) * 8 + lr;
    const int b_toff = (seg >> 1);
    const int l15 = lane & 15;

    float acc[5][4];
#pragma unroll
    for (int t = 0; t < 5; t++)
#pragma unroll
        for (int j = 0; j < 4; j++) acc[t][j] = 0.f;

#pragma unroll
    for (int s = 0; s < 4; s++) {
        unsigned a0 = relu_h2(*(const unsigned*)(pA0 + s * 16));
        unsigned a1 = relu_h2(*(const unsigned*)(pA1 + s * 16));
        unsigned a2 = relu_h2(*(const unsigned*)(pA0 + s * 16 + 8));
        unsigned a3 = relu_h2(*(const unsigned*)(pA1 + s * 16 + 8));

        unsigned b[5][2];
#pragma unroll
        for (int tp = 0; tp < 2; tp++) {
            unsigned bd = (unsigned)__cvta_generic_to_shared(
                sW + (s * 16 + b_kr) * SW2_PITCH + (2 * tp + b_toff) * 8);
            unsigned q0, q1, q2, q3;
            asm volatile("ldmatrix.sync.aligned.m8n8.x4.trans.shared.b16 {%0,%1,%2,%3}, [%4];"
                         : "=r"(q0), "=r"(q1), "=r"(q2), "=r"(q3) : "r"(bd));
            b[2 * tp][0] = q0; b[2 * tp][1] = q1;
            b[2 * tp + 1][0] = q2; b[2 * tp + 1][1] = q3;
        }
        {
            unsigned bd = (unsigned)__cvta_generic_to_shared(
                sW + (s * 16 + (l15 >> 3) * 8 + (l15 & 7)) * SW2_PITCH + 32);
            unsigned q0, q1;
            asm volatile("ldmatrix.sync.aligned.m8n8.x2.trans.shared.b16 {%0,%1}, [%2];"
                         : "=r"(q0), "=r"(q1) : "r"(bd));
            b[4][0] = q0; b[4][1] = q1;
        }
#pragma unroll
        for (int t = 0; t < 5; t++) {
            asm volatile(
                "mma.sync.aligned.m16n8k16.row.col.f32.f16.f16.f32 "
                "{%0,%1,%2,%3}, {%4,%5,%6,%7}, {%8,%9}, {%0,%1,%2,%3};"
                : "+f"(acc[t][0]), "+f"(acc[t][1]), "+f"(acc[t][2]), "+f"(acc[t][3])
                : "r"(a0), "r"(a1), "r"(a2), "r"(a3), "r"(b[t][0]), "r"(b[t][1]));
        }
    }

    const float dv0 = (r0 < M) ? g_dinv[r0] : 0.f;
    const float dv1 = (r1 < M) ? g_dinv[r1] : 0.f;
    const int cb = (lane & 3) * 2;
#pragma unroll
    for (int t = 0; t < 5; t++) {
        int col = t * 8 + cb;
        if (r0 < M)
            *(unsigned*)(C + (size_t)r0 * NCLS + col) = pack_h2(dv0 * acc[t][0], dv0 * acc[t][1]);
        if (r1 < M)
            *(unsigned*)(C + (size_t)r1 * NCLS + col) = pack_h2(dv1 * acc[t][2], dv1 * acc[t][3]);
    }
}

// ---------------- CSR aggregation (unweighted sum of dinv-scaled rows) ------
// out[d] = bias + dinv_d * (feat[d] + sum_j feat[src_j]);  feat already dinv-scaled.
template<int CH, bool ZERO_DEG, typename OutT>
__global__ void aggregate_kernel(const __half* __restrict__ feat,
                                 const float* __restrict__ bias,
                                 OutT* __restrict__ out) {
    constexpr int V4 = CH / 8;       // 8 (CH=64) or 5 (CH=40)
    constexpr int EP = 32 / V4;      // 4 or 6
    int node = (blockIdx.x * blockDim.x + threadIdx.x) >> 5;
    if (node >= N_NODES) return;
    int lane = threadIdx.x & 31;
    int eg = lane / V4;
    int c  = lane - eg * V4;
    bool act = eg < EP;

    if (ZERO_DEG && lane == 0) g_deg[node] = 0;

    const int beg = g_off[node];
    const int end = g_off[node + 1];

    float acc[8];
#pragma unroll
    for (int j = 0; j < 8; j++) acc[j] = 0.f;

    if (eg == 0) {                   // self-loop row (already dinv_d-scaled)
        uint4 f = ((const uint4*)(feat + (size_t)node * CH))[c];
        h8_to_f8(f, acc);
    }

    // software-pipelined edge loop; sentinel -1 skips tail slots
    int p = (act && beg + eg < end) ? g_adj[beg + eg] : -1;
    for (int k = beg; k < end; k += EP) {
        int kn = k + EP;
        int pn = (act && kn + eg < end) ? g_adj[kn + eg] : -1;
        if (p >= 0) {
            uint4 v = ((const uint4*)(feat + (size_t)p * CH))[c];
            float ff[8]; h8_to_f8(v, ff);
#pragma unroll
            for (int j = 0; j < 8; j++) acc[j] += ff[j];
        }
        p = pn;
    }

    const unsigned m = 0xffffffffu;
    if (EP == 4) {
#pragma unroll
        for (int j = 0; j < 8; j++) acc[j] += __shfl_down_sync(m, acc[j], 2 * V4);
#pragma unroll
        for (int j = 0; j < 8; j++) acc[j] += __shfl_down_sync(m, acc[j], V4);
    } else {  // EP == 6
#pragma unroll
        for (int j = 0; j < 8; j++) acc[j] += __shfl_down_sync(m, acc[j], 3 * V4);
#pragma unroll
        for (int j = 0; j < 8; j++) {
            float t = __shfl_down_sync(m, acc[j], 2 * V4);
            if (eg == 0) acc[j] += t;
        }
#pragma unroll
        for (int j = 0; j < 8; j++) {
            float t = __shfl_down_sync(m, acc[j], V4);
            if (eg == 0) acc[j] += t;
        }
    }

    if (eg == 0) {
        float dv = g_dinv[node];
        float4 b0 = ((const float4*)bias)[2 * c];
        float4 b1 = ((const float4*)bias)[2 * c + 1];
        float o0 = fmaf(dv, acc[0], b0.x), o1 = fmaf(dv, acc[1], b0.y);
        float o2 = fmaf(dv, acc[2], b0.z), o3 = fmaf(dv, acc[3], b0.w);
        float o4 = fmaf(dv, acc[4], b1.x), o5 = fmaf(dv, acc[5], b1.y);
        float o6 = fmaf(dv, acc[6], b1.z), o7 = fmaf(dv, acc[7], b1.w);
        if (sizeof(OutT) == 2) {
            uint4 u;
            u.x = pack_h2(o0, o1); u.y = pack_h2(o2, o3);
            u.z = pack_h2(o4, o5); u.w = pack_h2(o6, o7);
            ((uint4*)((__half*)out + (size_t)node * CH))[c] = u;
        } else {
            float4* po = (float4*)((float*)out + (size_t)node * CH);
            po[2 * c]     = make_float4(o0, o1, o2, o3);
            po[2 * c + 1] = make_float4(o4, o5, o6, o7);
        }
    }
}

// ---------------- launch ----------------------------------------------------
extern "C" void kernel_launch(void* const* d_in, const int* in_sizes, int n_in,
                              void* d_out, int out_size) {
    const float* x  = (const float*)d_in[0];
    const int*   ei = (const int*)d_in[1];
    const float* W1 = (const float*)d_in[2];
    const float* b1 = (const float*)d_in[3];
    const float* W2 = (const float*)d_in[4];
    const float* b2 = (const float*)d_in[5];
    float*       out = (float*)d_out;

    void *hw_p, *agg1_p, *h2w_p;
    cudaGetSymbolAddress(&hw_p,   g_hw);
    cudaGetSymbolAddress(&agg1_p, g_agg1);
    cudaGetSymbolAddress(&h2w_p,  g_h2w);

    constexpr int TPB = 256;

    // 1) degree histogram (dtype detect + lookback reset folded in)
    deg_kernel<<<NB_EDGE4, 256>>>(ei);
    // 2) single-kernel scan -> off/cur/dinv (gemm1 epilogue needs dinv)
    scan_kernel<<<SCAN_NB, SCAN_TPB>>>();
    // 3) gemm1 with dinv-scaling epilogue
    gemm1_kernel<<<(N_NODES + 127) / 128, 256>>>(x, W1, (__half*)hw_p, N_NODES);
    // 4) counting sort into dst-grouped plain-src adjacency
    fill_kernel<<<NB_EDGE4, 256>>>(ei);

    // 5) layer1 aggregation -> fp16 (bias + dinv_d * sum)
    const int nb_warps = (N_NODES * 32 + TPB - 1) / TPB;
    aggregate_kernel<HIDDEN, false, __half>
        <<<nb_warps, TPB>>>((const __half*)hw_p, b1, (__half*)agg1_p);

    // 6) gemm2 (tensor core, relu fused, dinv-scaling epilogue)
    gemm2_kernel<<<(N_NODES + 127) / 128, 256>>>((const __half*)agg1_p, W2,
                                                 (__half*)h2w_p, N_NODES);

    // 7) layer2 aggregation -> fp32 output (re-zeroes g_deg for next call)
    aggregate_kernel<NCLS, true, float>
        <<<nb_warps, TPB>>>((const __half*)h2w_p, b2, out);
}

// round 15
// speedup vs baseline: 1.9570x; 1.0249x over previous
#include <cuda_runtime.h>
#include <cuda_fp16.h>
#include <cstdint>

#define N_NODES 100000
#define N_EDGES 1600000
#define IN_CH   128
#define HIDDEN  64
#define NCLS    40

// ---------------- scratch (device globals; no allocation allowed) ----------
__device__ int   g_is64;
__device__ int   g_deg[N_NODES];       // zero at load; re-zeroed by agg2 tail
__device__ int   g_off[N_NODES + 1];
__device__ float g_dinv[N_NODES];
__device__ int   g_bsum[128];          // lookback partials (sentinel +1); reset by deg
__device__ int   g_rank[N_EDGES];      // edge's rank within its dst (from deg atomic)
__device__ int   g_adj[N_EDGES];       // plain src index, dst-grouped
__device__ __align__(16) __half g_hw  [(size_t)N_NODES * HIDDEN];  // dinv*(X@W1) fp16
__device__ __align__(16) __half g_agg1[(size_t)N_NODES * HIDDEN];  // layer1 agg (fp16)
__device__ __align__(16) __half g_h2w [(size_t)N_NODES * NCLS];    // dinv*(relu@W2) fp16

// ---------------- helpers ----------------------------------------------------
__device__ __forceinline__ void h8_to_f8(uint4 v, float* f) {
    float2 t;
    t = __half22float2(*(__half2*)&v.x); f[0] = t.x; f[1] = t.y;
    t = __half22float2(*(__half2*)&v.y); f[2] = t.x; f[3] = t.y;
    t = __half22float2(*(__half2*)&v.z); f[4] = t.x; f[5] = t.y;
    t = __half22float2(*(__half2*)&v.w); f[6] = t.x; f[7] = t.y;
}
__device__ __forceinline__ unsigned pack_h2(float a, float b) {
    __half2 h = __float22half2_rn(make_float2(a, b));
    return *(unsigned*)&h;
}
__device__ __forceinline__ unsigned relu_h2(unsigned v) {
    __half2 h = *(__half2*)&v;
    h = __hmax2(h, __half2half2(__ushort_as_half(0)));
    return *(unsigned*)&h;
}

#define NB_EDGE4 1563
#define EDGE4_T  (NB_EDGE4 * 256)
#define SCAN_NB  128
#define SCAN_TPB 256
#define SCAN_PER 4        // 128*256*4 = 131072 >= N_NODES

// ---------------- deg: dtype detect + degree histogram + rank capture -------
__global__ void deg_kernel(const int* __restrict__ w) {
    int v = w[2 * threadIdx.x + 1] | w[2 * ((int)threadIdx.x + 256) + 1];
    int is64 = !__syncthreads_or(v);
    if (blockIdx.x == 0) {
        if (threadIdx.x == 0) g_is64 = is64;
        if (threadIdx.x < SCAN_NB) g_bsum[threadIdx.x] = 0;
    }

    int idx = blockIdx.x * 256 + threadIdx.x;
#pragma unroll
    for (int j = 0; j < 4; j++) {
        int e = idx + j * EDGE4_T;
        if (e < N_EDGES) {
            int d = is64 ? w[2 * (N_EDGES + e)] : w[N_EDGES + e];
            if ((unsigned)d >= N_NODES) d = 0;
            g_rank[e] = atomicAdd(&g_deg[d], 1);   // recycle rank for fill
        }
    }
}

// ---------------- single-kernel exclusive scan (decoupled lookback) ---------
__global__ void scan_kernel() {
    __shared__ int p[SCAN_TPB];
    __shared__ int red[SCAN_TPB];
    const int t = threadIdx.x;
    const int bid = blockIdx.x;

    int base = (bid * SCAN_TPB + t) * SCAN_PER;
    int loc[SCAN_PER];
    int s = 0;
#pragma unroll
    for (int j = 0; j < SCAN_PER; j++) {
        int i = base + j;
        int d = (i < N_NODES) ? g_deg[i] : 0;
        loc[j] = s;
        s += d;
    }
    p[t] = s;
    __syncthreads();
    for (int o = 1; o < SCAN_TPB; o <<= 1) {
        int v = (t >= o) ? p[t - o] : 0;
        __syncthreads();
        p[t] += v;
        __syncthreads();
    }
    int total = p[SCAN_TPB - 1];

    if (t == 0) {
        __threadfence();
        atomicExch(&g_bsum[bid], total + 1);   // publish with sentinel
    }

    int v = 0;
    if (t < bid) {
        while ((v = atomicAdd(&g_bsum[t], 0)) == 0) { }
        v -= 1;
    }
    red[t] = v;
    __syncthreads();
    for (int o = SCAN_TPB / 2; o > 0; o >>= 1) {
        if (t < o) red[t] += red[t + o];
        __syncthreads();
    }
    int bpre = red[0];
    if (bid == SCAN_NB - 1 && t == 0) g_off[N_NODES] = bpre + total;

    int pre = bpre + ((t > 0) ? p[t - 1] : 0);
#pragma unroll
    for (int j = 0; j < SCAN_PER; j++) {
        int i = base + j;
        if (i < N_NODES) {
            g_off[i] = pre + loc[j];
            g_dinv[i] = rsqrtf((float)(g_deg[i] + 1));  // +1 self loop
        }
    }
}

// counting-sort edges by dst; position = off[d] + rank (no atomics)
__global__ void fill_kernel(const int* __restrict__ w) {
    int idx = blockIdx.x * 256 + threadIdx.x;
    int is64 = g_is64;
#pragma unroll
    for (int j = 0; j < 4; j++) {
        int e = idx + j * EDGE4_T;
        if (e < N_EDGES) {
            int s, d;
            if (is64) { s = w[2 * e]; d = w[2 * (N_EDGES + e)]; }
            else      { s = w[e];     d = w[N_EDGES + e]; }
            if ((unsigned)s >= N_NODES) s = 0;
            if ((unsigned)d >= N_NODES) d = 0;
            g_adj[g_off[d] + g_rank[e]] = s;
        }
    }
}

// ---------------- GEMM1 (tensor core, A direct from gmem, pipelined) --------
// fp16 C[M,64] = dinv[m] * (A[M,128](fp32) @ W[128,64]); 8 warps x 16 rows.
#define SW_PITCH 72

__global__ __launch_bounds__(256) void gemm1_kernel(const float* __restrict__ A,
                                                    const float* __restrict__ W,
                                                    __half* __restrict__ C, int M) {
    __shared__ __half sW[128 * SW_PITCH];
    const int tid = threadIdx.x;

    for (int i = tid; i < 128 * 16; i += 256) {
        int r  = i >> 4;
        int c4 = (i & 15) * 4;
        float4 a = *(const float4*)(W + r * HIDDEN + c4);
        *(uint2*)(sW + r * SW_PITCH + c4) = make_uint2(pack_h2(a.x, a.y), pack_h2(a.z, a.w));
    }
    __syncthreads();

    const int warp = tid >> 5, lane = tid & 31;
    const int r0 = blockIdx.x * 128 + warp * 16 + (lane >> 2);
    const int r1 = r0 + 8;
    const float* pA0 = A + (size_t)(r0 < M ? r0 : 0) * IN_CH + (lane & 3) * 2;
    const float* pA1 = A + (size_t)(r1 < M ? r1 : 0) * IN_CH + (lane & 3) * 2;

    const int lr  = lane & 7;
    const int seg = lane >> 3;
    const int b_kr   = (seg & 1) * 8 + lr;
    const int b_toff = (seg >> 1);

    float acc[8][4];
#pragma unroll
    for (int t = 0; t < 8; t++)
#pragma unroll
        for (int j = 0; j < 4; j++) acc[t][j] = 0.f;

    float2 f[2][4];
#pragma unroll
    for (int q = 0; q < 2; q++) {
        f[q][0] = *(const float2*)(pA0 + q * 16);
        f[q][1] = *(const float2*)(pA1 + q * 16);
        f[q][2] = *(const float2*)(pA0 + q * 16 + 8);
        f[q][3] = *(const float2*)(pA1 + q * 16 + 8);
    }

#pragma unroll
    for (int s = 0; s < 8; s++) {
        unsigned a0 = pack_h2(f[s & 1][0].x, f[s & 1][0].y);
        unsigned a1 = pack_h2(f[s & 1][1].x, f[s & 1][1].y);
        unsigned a2 = pack_h2(f[s & 1][2].x, f[s & 1][2].y);
        unsigned a3 = pack_h2(f[s & 1][3].x, f[s & 1][3].y);
        if (s + 2 < 8) {
            f[s & 1][0] = *(const float2*)(pA0 + (s + 2) * 16);
            f[s & 1][1] = *(const float2*)(pA1 + (s + 2) * 16);
            f[s & 1][2] = *(const float2*)(pA0 + (s + 2) * 16 + 8);
            f[s & 1][3] = *(const float2*)(pA1 + (s + 2) * 16 + 8);
        }

        unsigned b[8][2];
#pragma unroll
        for (int tp = 0; tp < 4; tp++) {
            unsigned bd = (unsigned)__cvta_generic_to_shared(
                sW + (s * 16 + b_kr) * SW_PITCH + (2 * tp + b_toff) * 8);
            unsigned q0, q1, q2, q3;
            asm volatile("ldmatrix.sync.aligned.m8n8.x4.trans.shared.b16 {%0,%1,%2,%3}, [%4];"
                         : "=r"(q0), "=r"(q1), "=r"(q2), "=r"(q3) : "r"(bd));
            b[2 * tp][0] = q0; b[2 * tp][1] = q1;
            b[2 * tp + 1][0] = q2; b[2 * tp + 1][1] = q3;
        }
#pragma unroll
        for (int t = 0; t < 8; t++) {
            asm volatile(
                "mma.sync.aligned.m16n8k16.row.col.f32.f16.f16.f32 "
                "{%0,%1,%2,%3}, {%4,%5,%6,%7}, {%8,%9}, {%0,%1,%2,%3};"
                : "+f"(acc[t][0]), "+f"(acc[t][1]), "+f"(acc[t][2]), "+f"(acc[t][3])
                : "r"(a0), "r"(a1), "r"(a2), "r"(a3), "r"(b[t][0]), "r"(b[t][1]));
        }
    }

    const float dv0 = (r0 < M) ? g_dinv[r0] : 0.f;
    const float dv1 = (r1 < M) ? g_dinv[r1] : 0.f;
    const int cb = (lane & 3) * 2;
#pragma unroll
    for (int t = 0; t < 8; t++) {
        int col = t * 8 + cb;
        if (r0 < M)
            *(unsigned*)(C + (size_t)r0 * HIDDEN + col) = pack_h2(dv0 * acc[t][0], dv0 * acc[t][1]);
        if (r1 < M)
            *(unsigned*)(C + (size_t)r1 * HIDDEN + col) = pack_h2(dv1 * acc[t][2], dv1 * acc[t][3]);
    }
}

// ---------------- GEMM2 (tensor core): fp16 C[M,40]=dinv*(relu(A)@W[64,40]) -
#define SW2_PITCH 40

__global__ __launch_bounds__(256) void gemm2_kernel(const __half* __restrict__ A,
                                                    const float* __restrict__ W,
                                                    __half* __restrict__ C, int M) {
    __shared__ __half sW[64 * SW2_PITCH];
    const int tid = threadIdx.x;

    for (int i = tid; i < 64 * 10; i += 256) {
        int r = i / 10, c4 = (i - r * 10) * 4;
        float4 a = *(const float4*)(W + r * NCLS + c4);
        *(uint2*)(sW + r * SW2_PITCH + c4) = make_uint2(pack_h2(a.x, a.y), pack_h2(a.z, a.w));
    }
    __syncthreads();

    const int warp = tid >> 5, lane = tid & 31;
    const int r0 = blockIdx.x * 128 + warp * 16 + (lane >> 2);
    const int r1 = r0 + 8;
    const __half* pA0 = A + (size_t)(r0 < M ? r0 : 0) * HIDDEN + (lane & 3) * 2;
    const __half* pA1 = A + (size_t)(r1 < M ? r1 : 0) * HIDDEN + (lane & 3) * 2;

    const int lr  = lane & 7;
    const int seg = lane >> 3;
    const int b_kr   = (seg & 1) * 8 + lr;
    const int b_toff = (seg >> 1);
    const int l15 = lane & 15;

    float acc[5][4];
#pragma unroll
    for (int t = 0; t < 5; t++)
#pragma unroll
        for (int j = 0; j < 4; j++) acc[t][j] = 0.f;

#pragma unroll
    for (int s = 0; s < 4; s++) {
        unsigned a0 = relu_h2(*(const unsigned*)(pA0 + s * 16));
        unsigned a1 = relu_h2(*(const unsigned*)(pA1 + s * 16));
        unsigned a2 = relu_h2(*(const unsigned*)(pA0 + s * 16 + 8));
        unsigned a3 = relu_h2(*(const unsigned*)(pA1 + s * 16 + 8));

        unsigned b[5][2];
#pragma unroll
        for (int tp = 0; tp < 2; tp++) {
            unsigned bd = (unsigned)__cvta_generic_to_shared(
                sW + (s * 16 + b_kr) * SW2_PITCH + (2 * tp + b_toff) * 8);
            unsigned q0, q1, q2, q3;
            asm volatile("ldmatrix.sync.aligned.m8n8.x4.trans.shared.b16 {%0,%1,%2,%3}, [%4];"
                         : "=r"(q0), "=r"(q1), "=r"(q2), "=r"(q3) : "r"(bd));
            b[2 * tp][0] = q0; b[2 * tp][1] = q1;
            b[2 * tp + 1][0] = q2; b[2 * tp + 1][1] = q3;
        }
        {
            unsigned bd = (unsigned)__cvta_generic_to_shared(
                sW + (s * 16 + (l15 >> 3) * 8 + (l15 & 7)) * SW2_PITCH + 32);
            unsigned q0, q1;
            asm volatile("ldmatrix.sync.aligned.m8n8.x2.trans.shared.b16 {%0,%1}, [%2];"
                         : "=r"(q0), "=r"(q1) : "r"(bd));
            b[4][0] = q0; b[4][1] = q1;
        }
#pragma unroll
        for (int t = 0; t < 5; t++) {
            asm volatile(
                "mma.sync.aligned.m16n8k16.row.col.f32.f16.f16.f32 "
                "{%0,%1,%2,%3}, {%4,%5,%6,%7}, {%8,%9}, {%0,%1,%2,%3};"
                : "+f"(acc[t][0]), "+f"(acc[t][1]), "+f"(acc[t][2]), "+f"(acc[t][3])
                : "r"(a0), "r"(a1), "r"(a2), "r"(a3), "r"(b[t][0]), "r"(b[t][1]));
        }
    }

    const float dv0 = (r0 < M) ? g_dinv[r0] : 0.f;
    const float dv1 = (r1 < M) ? g_dinv[r1] : 0.f;
    const int cb = (lane & 3) * 2;
#pragma unroll
    for (int t = 0; t < 5; t++) {
        int col = t * 8 + cb;
        if (r0 < M)
            *(unsigned*)(C + (size_t)r0 * NCLS + col) = pack_h2(dv0 * acc[t][0], dv0 * acc[t][1]);
        if (r1 < M)
            *(unsigned*)(C + (size_t)r1 * NCLS + col) = pack_h2(dv1 * acc[t][2], dv1 * acc[t][3]);
    }
}

// ---------------- CSR aggregation (unweighted sum of dinv-scaled rows) ------
// out[d] = bias + dinv_d * (feat[d] + sum_j feat[src_j]);  feat already dinv-scaled.
template<int CH, bool ZERO_DEG, typename OutT>
__global__ void aggregate_kernel(const __half* __restrict__ feat,
                                 const float* __restrict__ bias,
                                 OutT* __restrict__ out) {
    constexpr int V4 = CH / 8;       // 8 (CH=64) or 5 (CH=40)
    constexpr int EP = 32 / V4;      // 4 or 6
    int node = (blockIdx.x * blockDim.x + threadIdx.x) >> 5;
    if (node >= N_NODES) return;
    int lane = threadIdx.x & 31;
    int eg = lane / V4;
    int c  = lane - eg * V4;
    bool act = eg < EP;

    if (ZERO_DEG && lane == 0) g_deg[node] = 0;

    const int beg = g_off[node];
    const int end = g_off[node + 1];

    float acc[8];
#pragma unroll
    for (int j = 0; j < 8; j++) acc[j] = 0.f;

    if (eg == 0) {                   // self-loop row (already dinv_d-scaled)
        uint4 f = ((const uint4*)(feat + (size_t)node * CH))[c];
        h8_to_f8(f, acc);
    }

    int p = (act && beg + eg < end) ? g_adj[beg + eg] : -1;
    for (int k = beg; k < end; k += EP) {
        int kn = k + EP;
        int pn = (act && kn + eg < end) ? g_adj[kn + eg] : -1;
        if (p >= 0) {
            uint4 v = ((const uint4*)(feat + (size_t)p * CH))[c];
            float ff[8]; h8_to_f8(v, ff);
#pragma unroll
            for (int j = 0; j < 8; j++) acc[j] += ff[j];
        }
        p = pn;
    }

    const unsigned m = 0xffffffffu;
    if (EP == 4) {
#pragma unroll
        for (int j = 0; j < 8; j++) acc[j] += __shfl_down_sync(m, acc[j], 2 * V4);
#pragma unroll
        for (int j = 0; j < 8; j++) acc[j] += __shfl_down_sync(m, acc[j], V4);
    } else {  // EP == 6
#pragma unroll
        for (int j = 0; j < 8; j++) acc[j] += __shfl_down_sync(m, acc[j], 3 * V4);
#pragma unroll
        for (int j = 0; j < 8; j++) {
            float t = __shfl_down_sync(m, acc[j], 2 * V4);
            if (eg == 0) acc[j] += t;
        }
#pragma unroll
        for (int j = 0; j < 8; j++) {
            float t = __shfl_down_sync(m, acc[j], V4);
            if (eg == 0) acc[j] += t;
        }
    }

    if (eg == 0) {
        float dv = g_dinv[node];
        float4 b0 = ((const float4*)bias)[2 * c];
        float4 b1 = ((const float4*)bias)[2 * c + 1];
        float o0 = fmaf(dv, acc[0], b0.x), o1 = fmaf(dv, acc[1], b0.y);
        float o2 = fmaf(dv, acc[2], b0.z), o3 = fmaf(dv, acc[3], b0.w);
        float o4 = fmaf(dv, acc[4], b1.x), o5 = fmaf(dv, acc[5], b1.y);
        float o6 = fmaf(dv, acc[6], b1.z), o7 = fmaf(dv, acc[7], b1.w);
        if (sizeof(OutT) == 2) {
            uint4 u;
            u.x = pack_h2(o0, o1); u.y = pack_h2(o2, o3);
            u.z = pack_h2(o4, o5); u.w = pack_h2(o6, o7);
            ((uint4*)((__half*)out + (size_t)node * CH))[c] = u;
        } else {
            float4* po = (float4*)((float*)out + (size_t)node * CH);
            po[2 * c]     = make_float4(o0, o1, o2, o3);
            po[2 * c + 1] = make_float4(o4, o5, o6, o7);
        }
    }
}

// ---------------- launch ----------------------------------------------------
extern "C" void kernel_launch(void* const* d_in, const int* in_sizes, int n_in,
                              void* d_out, int out_size) {
    const float* x  = (const float*)d_in[0];
    const int*   ei = (const int*)d_in[1];
    const float* W1 = (const float*)d_in[2];
    const float* b1 = (const float*)d_in[3];
    const float* W2 = (const float*)d_in[4];
    const float* b2 = (const float*)d_in[5];
    float*       out = (float*)d_out;

    void *hw_p, *agg1_p, *h2w_p;
    cudaGetSymbolAddress(&hw_p,   g_hw);
    cudaGetSymbolAddress(&agg1_p, g_agg1);
    cudaGetSymbolAddress(&h2w_p,  g_h2w);

    constexpr int TPB = 256;

    // 1) degree histogram + per-edge rank capture
    deg_kernel<<<NB_EDGE4, 256>>>(ei);
    // 2) single-kernel scan -> off/dinv
    scan_kernel<<<SCAN_NB, SCAN_TPB>>>();
    // 3) gemm1 with dinv-scaling epilogue
    gemm1_kernel<<<(N_NODES + 127) / 128, 256>>>(x, W1, (__half*)hw_p, N_NODES);
    // 4) counting sort via off+rank (atomic-free)
    fill_kernel<<<NB_EDGE4, 256>>>(ei);

    // 5) layer1 aggregation -> fp16 (bias + dinv_d * sum)
    const int nb_warps = (N_NODES * 32 + TPB - 1) / TPB;
    aggregate_kernel<HIDDEN, false, __half>
        <<<nb_warps, TPB>>>((const __half*)hw_p, b1, (__half*)agg1_p);

    // 6) gemm2 (tensor core, relu fused, dinv-scaling epilogue)
    gemm2_kernel<<<(N_NODES + 127) / 128, 256>>>((const __half*)agg1_p, W2,
                                                 (__half*)h2w_p, N_NODES);

    // 7) layer2 aggregation -> fp32 output (re-zeroes g_deg for next call)
    aggregate_kernel<NCLS, true, float>
        <<<nb_warps, TPB>>>((const __half*)h2w_p, b2, out);
}